// round 13
// baseline (speedup 1.0000x reference)
#include <cuda_runtime.h>
#include <cuda_fp16.h>
#include <math.h>
#include <stdint.h>

#define BATCH   8
#define SEQ     2048
#define DMODEL  1024
#define DHEAD   128
#define MTOK    (BATCH*SEQ)          // 16384
#define NROUNDS 3
#define SCALE_F 0.08838834764831843f // 1/sqrt(128)
#define LOG2E_F 1.4426950408889634f
#define SLG_F   (SCALE_F*LOG2E_F)
#define POFF_F  6.0f                 // constant exponent offset (cancels via l)

// ---------------- device scratch (no runtime allocation allowed) -------------
__device__ __align__(256) __half g_qkv[3*MTOK*DHEAD];         // q,k,v fp16
__device__ __align__(256) __half g_curR[MTOK*DHEAD];          // fp16 copy of cur
__device__ __align__(256) float  g_Opart[2][MTOK*DHEAD];      // split-KV partials
__device__ __align__(256) float  g_lpart[2][MTOK];
__device__ __align__(256) __half g_wqkvr[3*DHEAD*DMODEL];
__device__ __align__(256) __half g_twr[DHEAD*DHEAD];
__device__ __align__(256) __half g_w2r[DHEAD*DHEAD];
__device__ __align__(256) __half g_wdr[DHEAD*DHEAD];
__device__ __align__(256) __half g_w1cr[DHEAD*DHEAD];
__device__ float g_cvec[DHEAD];
__device__ int   g_cnt[NROUNDS];
__device__ int   g_any[NROUNDS];

// ---------------- PTX helpers -------------------------------------------------
__device__ __forceinline__ uint32_t s2u(const void* p) {
    uint32_t a;
    asm("{ .reg .u64 t; cvta.to.shared.u64 t, %1; cvt.u32.u64 %0, t; }" : "=r"(a) : "l"(p));
    return a;
}
__device__ __forceinline__ void cp_async16(uint32_t dst, const void* src) {
    asm volatile("cp.async.cg.shared.global [%0], [%1], 16;" :: "r"(dst), "l"(src) : "memory");
}
#define CP_COMMIT() asm volatile("cp.async.commit_group;" ::: "memory")
#define CP_WAIT(N)  asm volatile("cp.async.wait_group %0;" :: "n"(N) : "memory")
#define U32(p) (*reinterpret_cast<const uint32_t*>(p))

__device__ __forceinline__ uint32_t pk(float lo, float hi) {
    __half2 h = __floats2half2_rn(lo, hi);
    return *reinterpret_cast<uint32_t*>(&h);
}
__device__ __forceinline__ float ex2f(float x) {
    float y;
    asm("ex2.approx.ftz.f32 %0, %1;" : "=f"(y) : "f"(x));
    return y;
}

__device__ __forceinline__ void mma_f16(
    float& c0, float& c1, float& c2, float& c3,
    uint32_t a0, uint32_t a1, uint32_t a2, uint32_t a3,
    uint32_t b0, uint32_t b1)
{
    asm volatile(
        "mma.sync.aligned.m16n8k16.row.col.f32.f16.f16.f32 "
        "{%0,%1,%2,%3}, {%4,%5,%6,%7}, {%8,%9}, {%0,%1,%2,%3};"
        : "+f"(c0), "+f"(c1), "+f"(c2), "+f"(c3)
        : "r"(a0), "r"(a1), "r"(a2), "r"(a3), "r"(b0), "r"(b1));
}

__device__ __forceinline__ void ldsm4(uint32_t& d0, uint32_t& d1, uint32_t& d2,
                                      uint32_t& d3, uint32_t addr)
{
    asm volatile("ldmatrix.sync.aligned.m8n8.x4.shared.b16 {%0,%1,%2,%3}, [%4];"
        : "=r"(d0), "=r"(d1), "=r"(d2), "=r"(d3) : "r"(addr));
}
__device__ __forceinline__ void ldsm4t(uint32_t& d0, uint32_t& d1, uint32_t& d2,
                                       uint32_t& d3, uint32_t addr)
{
    asm volatile("ldmatrix.sync.aligned.m8n8.x4.trans.shared.b16 {%0,%1,%2,%3}, [%4];"
        : "=r"(d0), "=r"(d1), "=r"(d2), "=r"(d3) : "r"(addr));
}

// ---------------- QKV GEMM (fp16 mma, fp32 x converted in-kernel) -------------
#define QSA 40
#define QTILE_H (128*QSA)
#define QSTG_H (2*QTILE_H)
#define QKV_SMEM_BYTES (2*QSTG_H*2)   // 40960

__global__ __launch_bounds__(256) void qkv_gemm(
    const float* __restrict__ X, const __half* __restrict__ W,
    __half* __restrict__ out)
{
    extern __shared__ char smraw[];
    __half* smh = (__half*)smraw;
    const uint32_t sm_u = s2u(smh);
    const int z = blockIdx.x;
    const __half* B = W + (size_t)z*DHEAD*DMODEL;
    __half* C = out + (size_t)z*MTOK*DHEAD;
    const int tid = threadIdx.x, lane = tid & 31, warp = tid >> 5;
    const int wm = (warp >> 1) * 32, wn = (warp & 1) * 64;
    const int m0 = blockIdx.y * 128;
    const int lrow = tid >> 3, lc4 = (tid & 7) * 4;
    const int brow = tid >> 2, bc8 = (tid & 3) * 8;
    const int g = lane >> 2, t4 = lane & 3;
    const int nK = DMODEL >> 5;   // 32

    float4 areg[4];
    {
        const float* Ag = X + (size_t)m0*DMODEL + lc4;
        #pragma unroll
        for (int it = 0; it < 4; it++)
            areg[it] = *reinterpret_cast<const float4*>(Ag + (size_t)(lrow+it*32)*DMODEL);
        #pragma unroll
        for (int itb = 0; itb < 2; itb++)
            cp_async16(sm_u + (uint32_t)(QTILE_H + (brow+itb*64)*QSA + bc8)*2u,
                       B + (size_t)(brow+itb*64)*DMODEL + bc8);
        CP_COMMIT();
        #pragma unroll
        for (int it = 0; it < 4; it++) {
            float4 v = areg[it];
            uint2 h2 = make_uint2(pk(v.x, v.y), pk(v.z, v.w));
            *reinterpret_cast<uint2*>(&smh[(lrow+it*32)*QSA + lc4]) = h2;
        }
    }

    float acc[2][8][4];
    #pragma unroll
    for (int mi = 0; mi < 2; mi++)
        #pragma unroll
        for (int ni = 0; ni < 8; ni++)
            #pragma unroll
            for (int j = 0; j < 4; j++) acc[mi][ni][j] = 0.f;

    for (int kt = 0; kt < nK; kt++) {
        const int cs = kt & 1;
        if (kt + 1 < nK) {
            const int ko = (kt+1)*32;
            const float* Ag = X + (size_t)m0*DMODEL + ko + lc4;
            #pragma unroll
            for (int it = 0; it < 4; it++)
                areg[it] = *reinterpret_cast<const float4*>(Ag + (size_t)(lrow+it*32)*DMODEL);
            const int ns = cs ^ 1;
            #pragma unroll
            for (int itb = 0; itb < 2; itb++)
                cp_async16(sm_u + (uint32_t)(ns*QSTG_H + QTILE_H + (brow+itb*64)*QSA + bc8)*2u,
                           B + (size_t)(brow+itb*64)*DMODEL + ko + bc8);
            CP_COMMIT();
            CP_WAIT(1);
        } else {
            CP_WAIT(0);
        }
        __syncthreads();

        const __half* Ash = smh + cs*QSTG_H;
        const __half* Bsh = Ash + QTILE_H;
        #pragma unroll
        for (int kk = 0; kk < 2; kk++) {
            const int k0 = kk*16 + 2*t4;
            uint32_t a[2][4];
            #pragma unroll
            for (int mi = 0; mi < 2; mi++) {
                const __half* ap = Ash + (wm + mi*16 + g)*QSA + k0;
                a[mi][0] = U32(ap);
                a[mi][1] = U32(ap + 8*QSA);
                a[mi][2] = U32(ap + 8);
                a[mi][3] = U32(ap + 8*QSA + 8);
            }
            #pragma unroll
            for (int ni = 0; ni < 8; ni++) {
                const __half* bp = Bsh + (wn + ni*8 + g)*QSA + k0;
                uint32_t b0 = U32(bp), b1 = U32(bp + 8);
                #pragma unroll
                for (int mi = 0; mi < 2; mi++)
                    mma_f16(acc[mi][ni][0], acc[mi][ni][1], acc[mi][ni][2], acc[mi][ni][3],
                            a[mi][0], a[mi][1], a[mi][2], a[mi][3], b0, b1);
            }
        }
        if (kt + 1 < nK) {
            const int ns = cs ^ 1;
            __half* Ad = smh + ns*QSTG_H;
            #pragma unroll
            for (int it = 0; it < 4; it++) {
                float4 v = areg[it];
                uint2 h2 = make_uint2(pk(v.x, v.y), pk(v.z, v.w));
                *reinterpret_cast<uint2*>(&Ad[(lrow+it*32)*QSA + lc4]) = h2;
            }
        }
        __syncthreads();
    }

    #pragma unroll
    for (int mi = 0; mi < 2; mi++) {
        const int rA = m0 + wm + mi*16 + g, rB = rA + 8;
        #pragma unroll
        for (int ni = 0; ni < 8; ni++) {
            const int c0 = wn + ni*8 + 2*t4;
            *reinterpret_cast<__half2*>(C + (size_t)rA*DHEAD + c0) =
                __floats2half2_rn(acc[mi][ni][0], acc[mi][ni][1]);
            *reinterpret_cast<__half2*>(C + (size_t)rB*DHEAD + c0) =
                __floats2half2_rn(acc[mi][ni][2], acc[mi][ni][3]);
        }
    }
}

// ---------------- split-KV flash attention (fp16 mma, fixed-base softmax) -----
// grid (SEQ/128, BATCH, 2); z selects KV half. Q lives in smem (reg relief);
// partial unnormalized O (fp32) + l written per z; combined later.
#define SKV 136
#define FQ_OFF 0
#define FK_OFF 34816
#define FV_OFF (2*34816)
#define FL_SMEM_BYTES (3*34816)   // 104448

__global__ __launch_bounds__(256, 2) void flash_attn(
    const __half* __restrict__ q, const __half* __restrict__ k,
    const __half* __restrict__ v, float* __restrict__ Opart,
    float* __restrict__ lpart)
{
    extern __shared__ char smraw[];
    const uint32_t sm_u = s2u(smraw);
    const int b   = blockIdx.y;
    const int qb  = blockIdx.x * 128;
    const int z   = blockIdx.z;
    const int tid = threadIdx.x, lane = tid & 31, warp = tid >> 5;
    const int g   = lane >> 2, t4 = lane & 3;

    const __half* qB = q + ((size_t)b*SEQ + qb)*DHEAD;
    const __half* kB = k + ((size_t)b*SEQ + (size_t)z*(SEQ/2))*DHEAD;
    const __half* vB = v + ((size_t)b*SEQ + (size_t)z*(SEQ/2))*DHEAD;

    const int kc = tid >> 4;          // KV tile loads: 0..15 (+16/iter, 4 iters)
    const int kf = (tid & 15) * 8;

    // Q tile load: 128 rows x 128 halves; 2 threads/row, 8 cp.async each
    {
        const int qrow = tid >> 1, qc = (tid & 1) * 64;
        #pragma unroll
        for (int it = 0; it < 8; it++)
            cp_async16(sm_u + (uint32_t)(FQ_OFF/2 + qrow*SKV + qc + it*8)*2u,
                       qB + (size_t)qrow*DHEAD + qc + it*8);
        // prefetch KV tile 0
        #pragma unroll
        for (int it = 0; it < 4; it++) {
            cp_async16(sm_u + (uint32_t)(FK_OFF + ((kc + it*16)*SKV + kf)*2),
                       kB + (size_t)(kc + it*16)*DHEAD + kf);
            cp_async16(sm_u + (uint32_t)(FV_OFF + ((kc + it*16)*SKV + kf)*2),
                       vB + (size_t)(kc + it*16)*DHEAD + kf);
        }
        CP_COMMIT();
    }

    // ldmatrix per-lane offsets
    const uint32_t qOff = sm_u + FQ_OFF +
        (uint32_t)(((warp*16 + (lane & 7) + 8*((lane >> 3) & 1))*SKV + (lane >> 4)*8) * 2);
    const int krow = (lane >> 4)*8 + (lane & 7);
    const int kcol = ((lane >> 3) & 1) * 8;

    float oacc[16][4];
    #pragma unroll
    for (int ni = 0; ni < 16; ni++)
        #pragma unroll
        for (int j = 0; j < 4; j++) oacc[ni][j] = 0.f;
    float l0 = 0.f, l1 = 0.f;

    const int nTiles = (SEQ/2) / 64;  // 16
    for (int t = 0; t < nTiles; t++) {
        const int cs = t & 1;
        if (t + 1 < nTiles) {
            const int ns = cs ^ 1;
            const int kv1 = (t+1) * 64;
            #pragma unroll
            for (int it = 0; it < 4; it++) {
                cp_async16(sm_u + (uint32_t)(FK_OFF + ns*64*SKV*2 + ((kc + it*16)*SKV + kf)*2),
                           kB + (size_t)(kv1 + kc + it*16)*DHEAD + kf);
                cp_async16(sm_u + (uint32_t)(FV_OFF + ns*64*SKV*2 + ((kc + it*16)*SKV + kf)*2),
                           vB + (size_t)(kv1 + kc + it*16)*DHEAD + kf);
            }
            CP_COMMIT();
            CP_WAIT(1);
        } else {
            CP_WAIT(0);
        }
        __syncthreads();

        const uint32_t kb0 = sm_u + FK_OFF + (uint32_t)(cs*64*SKV + krow*SKV + kcol)*2u;
        const uint32_t vb0 = sm_u + FV_OFF + (uint32_t)(cs*64*SKV + lane*SKV)*2u;

        float sacc[8][4];
        #pragma unroll
        for (int ni = 0; ni < 8; ni++)
            #pragma unroll
            for (int j = 0; j < 4; j++) sacc[ni][j] = 0.f;
        #pragma unroll
        for (int ks = 0; ks < 8; ks++) {
            uint32_t a0, a1, a2, a3;
            ldsm4(a0, a1, a2, a3, qOff + (uint32_t)(ks*16)*2u);
            #pragma unroll
            for (int nj = 0; nj < 4; nj++) {
                uint32_t b0, b1, b2, b3;
                ldsm4(b0, b1, b2, b3, kb0 + (uint32_t)(nj*16*SKV + ks*16)*2u);
                mma_f16(sacc[2*nj][0], sacc[2*nj][1], sacc[2*nj][2], sacc[2*nj][3],
                        a0, a1, a2, a3, b0, b1);
                mma_f16(sacc[2*nj+1][0], sacc[2*nj+1][1], sacc[2*nj+1][2], sacc[2*nj+1][3],
                        a0, a1, a2, a3, b2, b3);
            }
        }

        // fixed-base softmax: P = exp2(s*scale*log2e - C); C cancels in combine
        float rs0 = 0.f, rs1 = 0.f;
        uint32_t pa[4][4];
        #pragma unroll
        for (int j = 0; j < 4; j++) {
            const int n0i = 2*j, n1i = 2*j + 1;
            float p00 = ex2f(fmaf(sacc[n0i][0], SLG_F, -POFF_F));
            float p01 = ex2f(fmaf(sacc[n0i][1], SLG_F, -POFF_F));
            float p02 = ex2f(fmaf(sacc[n0i][2], SLG_F, -POFF_F));
            float p03 = ex2f(fmaf(sacc[n0i][3], SLG_F, -POFF_F));
            float p10 = ex2f(fmaf(sacc[n1i][0], SLG_F, -POFF_F));
            float p11 = ex2f(fmaf(sacc[n1i][1], SLG_F, -POFF_F));
            float p12 = ex2f(fmaf(sacc[n1i][2], SLG_F, -POFF_F));
            float p13 = ex2f(fmaf(sacc[n1i][3], SLG_F, -POFF_F));
            rs0 += p00 + p01 + p10 + p11;
            rs1 += p02 + p03 + p12 + p13;
            pa[j][0] = pk(p00, p01);
            pa[j][1] = pk(p02, p03);
            pa[j][2] = pk(p10, p11);
            pa[j][3] = pk(p12, p13);
        }
        rs0 += __shfl_xor_sync(0xffffffffu, rs0, 1);
        rs0 += __shfl_xor_sync(0xffffffffu, rs0, 2);
        rs1 += __shfl_xor_sync(0xffffffffu, rs1, 1);
        rs1 += __shfl_xor_sync(0xffffffffu, rs1, 2);
        l0 += rs0;
        l1 += rs1;

        #pragma unroll
        for (int jp = 0; jp < 2; jp++) {
            const uint32_t ab = vb0 + (uint32_t)(jp*32*SKV)*2u;
            #pragma unroll
            for (int ni = 0; ni < 16; ni++) {
                uint32_t b0, b1, b2, b3;
                ldsm4t(b0, b1, b2, b3, ab + ni*16);
                mma_f16(oacc[ni][0], oacc[ni][1], oacc[ni][2], oacc[ni][3],
                        pa[2*jp][0], pa[2*jp][1], pa[2*jp][2], pa[2*jp][3], b0, b1);
                mma_f16(oacc[ni][0], oacc[ni][1], oacc[ni][2], oacc[ni][3],
                        pa[2*jp+1][0], pa[2*jp+1][1], pa[2*jp+1][2], pa[2*jp+1][3], b2, b3);
            }
        }
        __syncthreads();
    }

    // epilogue: write unnormalized partials
    float* Oz = Opart + (size_t)z*MTOK*DHEAD;
    float* lz = lpart + (size_t)z*MTOK;
    const size_t rowA = (size_t)b*SEQ + qb + warp*16 + g;
    const size_t rowB = rowA + 8;
    #pragma unroll
    for (int ni = 0; ni < 16; ni++) {
        const int c0 = ni*8 + 2*t4;
        float2 v0, v1;
        v0.x = oacc[ni][0]; v0.y = oacc[ni][1];
        v1.x = oacc[ni][2]; v1.y = oacc[ni][3];
        *reinterpret_cast<float2*>(Oz + rowA*DHEAD + c0) = v0;
        *reinterpret_cast<float2*>(Oz + rowB*DHEAD + c0) = v1;
    }
    if (t4 == 0) { lz[rowA] = l0; lz[rowB] = l1; }
}

// combine: cur = (O0+O1)/(l0+l1); curR = fp16(cur)
__global__ __launch_bounds__(256) void flash_combine(
    const float* __restrict__ Opart, const float* __restrict__ lpart,
    float* __restrict__ cur, __half* __restrict__ curR)
{
    const int idx = blockIdx.x * 256 + threadIdx.x;   // over MTOK*DHEAD/4
    const int row = idx >> 5;
    const float inv = 1.f / (lpart[row] + lpart[MTOK + row]);
    float4 a = reinterpret_cast<const float4*>(Opart)[idx];
    float4 c = reinterpret_cast<const float4*>(Opart + (size_t)MTOK*DHEAD)[idx];
    a.x = (a.x + c.x) * inv; a.y = (a.y + c.y) * inv;
    a.z = (a.z + c.z) * inv; a.w = (a.w + c.w) * inv;
    reinterpret_cast<float4*>(cur)[idx] = a;
    __half2 h0 = __floats2half2_rn(a.x, a.y);
    __half2 h1 = __floats2half2_rn(a.z, a.w);
    reinterpret_cast<__half2*>(curR)[2*idx]   = h0;
    reinterpret_cast<__half2*>(curR)[2*idx+1] = h1;
}

// ---------------- persistent merged rounds kernel (fp16, 256 thr, ldmatrix) ---
#define HSMS 136
#define RB_T0   0
#define RB_T1   34816
#define RB_T2   69632
#define RB_T3   104448
#define RB_T4   139264
#define RB_RED  174080
#define RB_ACT  176128
#define RALL_SMEM_BYTES (RB_ACT + 128*4)   // 176640
#define ZFS 132

__device__ __forceinline__ void load_tile128h(uint32_t sdst_bytes,
                                              const __half* __restrict__ src, int tid)
{
    const int row = tid >> 4, c8 = (tid & 15) * 8;
    #pragma unroll
    for (int it = 0; it < 8; it++)
        cp_async16(sdst_bytes + (uint32_t)((row + it*16)*HSMS + c8)*2u,
                   src + (size_t)(row + it*16)*128 + c8);
}

__device__ __forceinline__ void mma_128x128h(uint32_t aAddr, uint32_t bAddr,
                                             float acc[2][8][4])
{
    #pragma unroll
    for (int ks = 0; ks < 8; ks++) {
        uint32_t a[2][4];
        #pragma unroll
        for (int mi = 0; mi < 2; mi++)
            ldsm4(a[mi][0], a[mi][1], a[mi][2], a[mi][3],
                  aAddr + (uint32_t)(mi*16*HSMS + ks*16)*2u);
        #pragma unroll
        for (int nj = 0; nj < 4; nj++) {
            uint32_t b0, b1, b2, b3;
            ldsm4(b0, b1, b2, b3, bAddr + (uint32_t)(nj*16*HSMS + ks*16)*2u);
            #pragma unroll
            for (int mi = 0; mi < 2; mi++) {
                mma_f16(acc[mi][2*nj][0], acc[mi][2*nj][1], acc[mi][2*nj][2], acc[mi][2*nj][3],
                        a[mi][0], a[mi][1], a[mi][2], a[mi][3], b0, b1);
                mma_f16(acc[mi][2*nj+1][0], acc[mi][2*nj+1][1], acc[mi][2*nj+1][2], acc[mi][2*nj+1][3],
                        a[mi][0], a[mi][1], a[mi][2], a[mi][3], b2, b3);
            }
        }
    }
}

#define ZERO_ACC(acc) { \
    _Pragma("unroll") for (int mi = 0; mi < 2; mi++) \
        _Pragma("unroll") for (int ni = 0; ni < 8; ni++) \
            _Pragma("unroll") for (int j = 0; j < 4; j++) acc[mi][ni][j] = 0.f; }

__global__ __launch_bounds__(256) void rounds_all(
    float* __restrict__ cur, const __half* __restrict__ curR,
    const __half* __restrict__ tw, const __half* __restrict__ wd,
    const __half* __restrict__ w1c, const __half* __restrict__ w2,
    const float* __restrict__ cvec, const float* __restrict__ b1,
    const float* __restrict__ b2, const float* __restrict__ gw,
    const float* __restrict__ gb,
    int* __restrict__ cnt, int* __restrict__ anyf)
{
    extern __shared__ char smraw[];
    __half* smh = (__half*)smraw;
    const uint32_t sm_u = s2u(smraw);
    float* ZF  = reinterpret_cast<float*>(smraw + RB_T1);
    float* red = reinterpret_cast<float*>(smraw + RB_RED);
    int* s_act = reinterpret_cast<int*>(smraw + RB_ACT);
    __shared__ int s_flag, s_any;
    const int tid = threadIdx.x, lane = tid & 31, warp = tid >> 5;
    const int wm = (warp >> 1) * 32, wn = (warp & 1) * 64;
    const int g = lane >> 2, t4 = lane & 3;
    const int m0 = blockIdx.x * 128;

    const uint32_t aOff = (uint32_t)(((wm + (lane & 7) + 8*((lane >> 3) & 1))*HSMS
                                      + (lane >> 4)*8) * 2);
    const uint32_t bOff = (uint32_t)(((wn + (lane >> 4)*8 + (lane & 7))*HSMS
                                      + ((lane >> 3) & 1)*8) * 2);

    load_tile128h(sm_u + RB_T0, curR + (size_t)m0*128, tid);
    load_tile128h(sm_u + RB_T1, tw, tid);
    load_tile128h(sm_u + RB_T2, wd, tid);
    load_tile128h(sm_u + RB_T3, w1c, tid);
    load_tile128h(sm_u + RB_T4, w2, tid);
    CP_COMMIT(); CP_WAIT(0);
    if (tid < 128) s_act[tid] = 1;
    if (tid == 0) { s_flag = 1; s_any = 0; }
    __syncthreads();

    float acc[2][8][4];

    ZERO_ACC(acc);
    mma_128x128h(sm_u + RB_T0 + aOff, sm_u + RB_T1 + bOff, acc);
    __syncthreads();
    {
        __half* Ps = smh + RB_T1/2;
        #pragma unroll
        for (int mi = 0; mi < 2; mi++) {
            const int rA = wm + mi*16 + g, rB = rA + 8;
            #pragma unroll
            for (int ni = 0; ni < 8; ni++) {
                const int c0 = wn + ni*8 + 2*t4;
                *reinterpret_cast<__half2*>(&Ps[rA*HSMS + c0]) =
                    __floats2half2_rn(acc[mi][ni][0], acc[mi][ni][1]);
                *reinterpret_cast<__half2*>(&Ps[rB*HSMS + c0]) =
                    __floats2half2_rn(acc[mi][ni][2], acc[mi][ni][3]);
            }
        }
    }
    __syncthreads();
    ZERO_ACC(acc);
    mma_128x128h(sm_u + RB_T1 + aOff, sm_u + RB_T2 + bOff, acc);
    __syncthreads();
    {
        #pragma unroll
        for (int mi = 0; mi < 2; mi++) {
            const int rA = wm + mi*16 + g, rB = rA + 8;
            #pragma unroll
            for (int ni = 0; ni < 8; ni++) {
                const int c0 = wn + ni*8 + 2*t4;
                float2 v0, v1;
                v0.x = acc[mi][ni][0]; v0.y = acc[mi][ni][1];
                v1.x = acc[mi][ni][2]; v1.y = acc[mi][ni][3];
                *reinterpret_cast<float2*>(&ZF[rA*ZFS + c0]) = v0;
                *reinterpret_cast<float2*>(&ZF[rB*ZFS + c0]) = v1;
            }
        }
    }
    __syncthreads();

    for (int r = 0; r < NROUNDS; r++) {
        ZERO_ACC(acc);
        mma_128x128h(sm_u + RB_T0 + aOff, sm_u + RB_T3 + bOff, acc);
        __syncthreads();

        float amr[4];
        #pragma unroll
        for (int mi = 0; mi < 2; mi++) {
            const int rA = wm + mi*16 + g, rB = rA + 8;
            const float amA = s_act[rA] ? 1.f : 0.f;
            const float amB = s_act[rB] ? 1.f : 0.f;
            amr[mi*2] = amA; amr[mi*2+1] = amB;
            #pragma unroll
            for (int ni = 0; ni < 8; ni++) {
                const int c0 = wn + ni*8 + 2*t4;
                float2 zA = *reinterpret_cast<const float2*>(&ZF[rA*ZFS + c0]);
                float2 zB = *reinterpret_cast<const float2*>(&ZF[rB*ZFS + c0]);
                float2 cc = *reinterpret_cast<const float2*>(cvec + c0);
                float2 bb = *reinterpret_cast<const float2*>(b1 + c0);
                float h00 = fmaxf(fmaf(amA, acc[mi][ni][0] + zA.x + cc.x, bb.x), 0.f);
                float h01 = fmaxf(fmaf(amA, acc[mi][ni][1] + zA.y + cc.y, bb.y), 0.f);
                float h10 = fmaxf(fmaf(amB, acc[mi][ni][2] + zB.x + cc.x, bb.x), 0.f);
                float h11 = fmaxf(fmaf(amB, acc[mi][ni][3] + zB.y + cc.y, bb.y), 0.f);
                *reinterpret_cast<__half2*>(&smh[rA*HSMS + c0]) = __floats2half2_rn(h00, h01);
                *reinterpret_cast<__half2*>(&smh[rB*HSMS + c0]) = __floats2half2_rn(h10, h11);
            }
        }
        __syncthreads();

        ZERO_ACC(acc);
        mma_128x128h(sm_u + RB_T0 + aOff, sm_u + RB_T4 + bOff, acc);

        const int flg = s_flag;
        float d1[4] = {0,0,0,0}, nn[4] = {0,0,0,0};
        #pragma unroll
        for (int mi = 0; mi < 2; mi++) {
            const int rA = wm + mi*16 + g, rB = rA + 8;
            const float amA = amr[mi*2], amB = amr[mi*2+1];
            #pragma unroll
            for (int ni = 0; ni < 8; ni++) {
                const int c0 = wn + ni*8 + 2*t4;
                float2 cA = *reinterpret_cast<const float2*>(cur + (size_t)(m0+rA)*128 + c0);
                float2 cB = *reinterpret_cast<const float2*>(cur + (size_t)(m0+rB)*128 + c0);
                float2 bb = *reinterpret_cast<const float2*>(b2 + c0);
                float2 g1 = *reinterpret_cast<const float2*>(gw + c0);
                float2 g2 = *reinterpret_cast<const float2*>(gw + 128 + c0);
                float syA0 = acc[mi][ni][0] + bb.x, syA1 = acc[mi][ni][1] + bb.y;
                float syB0 = acc[mi][ni][2] + bb.x, syB1 = acc[mi][ni][3] + bb.y;
                float acA0 = cA.x * amA, acA1 = cA.y * amA;
                float acB0 = cB.x * amB, acB1 = cB.y * amB;
                d1[mi*2]   += acA0*g1.x + syA0*g2.x + acA1*g1.y + syA1*g2.y;
                d1[mi*2+1] += acB0*g1.x + syB0*g2.x + acB1*g1.y + syB1*g2.y;
                float dA0 = syA0-acA0, dA1 = syA1-acA1;
                float dB0 = syB0-acB0, dB1 = syB1-acB1;
                nn[mi*2]   += dA0*dA0 + dA1*dA1;
                nn[mi*2+1] += dB0*dB0 + dB1*dB1;
            }
        }
        #pragma unroll
        for (int j = 0; j < 4; j++) {
            d1[j] += __shfl_xor_sync(0xffffffffu, d1[j], 1);
            d1[j] += __shfl_xor_sync(0xffffffffu, d1[j], 2);
            nn[j] += __shfl_xor_sync(0xffffffffu, nn[j], 1);
            nn[j] += __shfl_xor_sync(0xffffffffu, nn[j], 2);
        }
        if (t4 == 0) {
            const int hf = (warp & 1) * 2;
            #pragma unroll
            for (int mi = 0; mi < 2; mi++) {
                const int rA = wm + mi*16 + g, rB = rA + 8;
                red[rA*4 + hf]     = d1[mi*2];
                red[rA*4 + hf + 1] = nn[mi*2];
                red[rB*4 + hf]     = d1[mi*2+1];
                red[rB*4 + hf + 1] = nn[mi*2+1];
            }
        }
        __syncthreads();

        const float gbv = gb[0];
        #pragma unroll
        for (int mi = 0; mi < 2; mi++) {
            const int rA = wm + mi*16 + g, rB = rA + 8;
            const float amA = amr[mi*2], amB = amr[mi*2+1];
            float gdA = red[rA*4+0] + red[rA*4+2] + gbv;
            float gdB = red[rB*4+0] + red[rB*4+2] + gbv;
            float n2A = red[rA*4+1] + red[rA*4+3];
            float n2B = red[rB*4+1] + red[rB*4+3];
            float gateA = 1.f / (1.f + expf(-gdA));
            float gateB = 1.f / (1.f + expf(-gdB));
            int stableA = (gateA * 0.1f * sqrtf(n2A)) < 0.1f;
            int stableB = (gateB * 0.1f * sqrtf(n2B)) < 0.1f;
            #pragma unroll
            for (int ni = 0; ni < 8; ni++) {
                const int c0 = wn + ni*8 + 2*t4;
                float2 cA = *reinterpret_cast<const float2*>(cur + (size_t)(m0+rA)*128 + c0);
                float2 cB = *reinterpret_cast<const float2*>(cur + (size_t)(m0+rB)*128 + c0);
                float2 bb = *reinterpret_cast<const float2*>(b2 + c0);
                float syA0 = acc[mi][ni][0] + bb.x, syA1 = acc[mi][ni][1] + bb.y;
                float syB0 = acc[mi][ni][2] + bb.x, syB1 = acc[mi][ni][3] + bb.y;
                float2 o0, o1;
                o0.x = cA.x; o0.y = cA.y; o1.x = cB.x; o1.y = cB.y;
                if (flg) {
                    o0.x += gateA * (syA0 - cA.x*amA) * 0.1f;
                    o0.y += gateA * (syA1 - cA.y*amA) * 0.1f;
                    o1.x += gateB * (syB0 - cB.x*amB) * 0.1f;
                    o1.y += gateB * (syB1 - cB.y*amB) * 0.1f;
                }
                *reinterpret_cast<float2*>(cur + (size_t)(m0+rA)*128 + c0) = o0;
                *reinterpret_cast<float2*>(cur + (size_t)(m0+rB)*128 + c0) = o1;
                *reinterpret_cast<__half2*>(&smh[rA*HSMS + c0]) = __floats2half2_rn(o0.x, o0.y);
                *reinterpret_cast<__half2*>(&smh[rB*HSMS + c0]) = __floats2half2_rn(o1.x, o1.y);
            }
            if ((warp & 1) == 0 && t4 == 0) {
                int actA = amA > 0.f, actB = amB > 0.f;
                int naA = actA && !stableA;
                int naB = actB && !stableB;
                if (flg) { s_act[rA] = naA; s_act[rB] = naB; }
                int effA = flg ? naA : actA;
                int effB = flg ? naB : actB;
                if (effA | effB) s_any = 1;
            }
        }
        __syncthreads();

        if (r + 1 < NROUNDS) {
            if (tid == 0) {
                if (s_any) atomicOr(&anyf[r], 1);
                __threadfence();
                atomicAdd(&cnt[r], 1);
                while (atomicAdd(&cnt[r], 0) < (int)gridDim.x) {}
                s_flag = (atomicOr(&anyf[r], 0) != 0) ? 1 : 0;
                s_any = 0;
            }
            __syncthreads();
        }
    }
}

// ---------------- single prep kernel (fp16 weight copies) ---------------------
__global__ void prep_all(
    const float* __restrict__ wq, const float* __restrict__ wk,
    const float* __restrict__ wv, const float* __restrict__ tw,
    const float* __restrict__ w2, const float* __restrict__ w1,
    const float* __restrict__ tb, const float* __restrict__ ab,
    __half* __restrict__ wqkvr, __half* __restrict__ twr,
    __half* __restrict__ w2r, __half* __restrict__ wdr,
    __half* __restrict__ w1cr, float* __restrict__ cvec,
    int* __restrict__ cnt, int* __restrict__ anyf)
{
    int idx = blockIdx.x * blockDim.x + threadIdx.x;
    const int WN4 = DHEAD*DMODEL/4;
    const int T4  = DHEAD*DHEAD/4;
    if (idx < 3*WN4) {
        const float* src = (idx < WN4) ? wq : (idx < 2*WN4 ? wk : wv);
        int off = (idx < WN4) ? idx : (idx < 2*WN4 ? idx - WN4 : idx - 2*WN4);
        float4 vv = reinterpret_cast<const float4*>(src)[off];
        reinterpret_cast<__half2*>(wqkvr)[2*idx]   = __floats2half2_rn(vv.x, vv.y);
        reinterpret_cast<__half2*>(wqkvr)[2*idx+1] = __floats2half2_rn(vv.z, vv.w);
        return;
    }
    idx -= 3*WN4;
    if (idx < T4) {
        float4 vv = reinterpret_cast<const float4*>(tw)[idx];
        reinterpret_cast<__half2*>(twr)[2*idx]   = __floats2half2_rn(vv.x, vv.y);
        reinterpret_cast<__half2*>(twr)[2*idx+1] = __floats2half2_rn(vv.z, vv.w);
        return;
    }
    idx -= T4;
    if (idx < T4) {
        float4 vv = reinterpret_cast<const float4*>(w2)[idx];
        reinterpret_cast<__half2*>(w2r)[2*idx]   = __floats2half2_rn(vv.x, vv.y);
        reinterpret_cast<__half2*>(w2r)[2*idx+1] = __floats2half2_rn(vv.z, vv.w);
        return;
    }
    idx -= T4;
    if (idx < DHEAD*DHEAD) {
        int j = idx >> 7, i = idx & 127;
        wdr[idx]  = __float2half_rn(w1[j*384 + i] - w1[j*384 + 128 + i]);
        w1cr[idx] = __float2half_rn(w1[j*384 + 256 + i]);
        return;
    }
    idx -= DHEAD*DHEAD;
    if (idx < DHEAD) {
        float s = 0.f;
        for (int i = 0; i < 128; i++)
            s += tb[i]*w1[idx*384 + i] + ab[i]*w1[idx*384 + 128 + i];
        cvec[idx] = s;
        return;
    }
    idx -= DHEAD;
    if (idx < NROUNDS) { cnt[idx] = 0; return; }
    idx -= NROUNDS;
    if (idx < NROUNDS) { anyf[idx] = 0; return; }
}
#define PREP_ITEMS (3*(DHEAD*DMODEL/4) + 2*(DHEAD*DHEAD/4) + DHEAD*DHEAD + DHEAD + 2*NROUNDS)

// ---------------- launch ------------------------------------------------------
extern "C" void kernel_launch(void* const* d_in, const int* in_sizes, int n_in,
                              void* d_out, int out_size)
{
    (void)in_sizes; (void)n_in; (void)out_size;
    const float* x  = (const float*)d_in[0];
    const float* wq = (const float*)d_in[1];
    const float* wk = (const float*)d_in[2];
    const float* wv = (const float*)d_in[3];
    const float* tw = (const float*)d_in[4];
    const float* tb = (const float*)d_in[5];
    const float* ab = (const float*)d_in[6];
    const float* w1 = (const float*)d_in[7];
    const float* b1 = (const float*)d_in[8];
    const float* w2 = (const float*)d_in[9];
    const float* b2 = (const float*)d_in[10];
    const float* gw = (const float*)d_in[11];
    const float* gb = (const float*)d_in[12];
    float* cur = (float*)d_out;

    __half *qkv,*curR,*wqkvr,*twr,*w2r,*wdr,*w1cr;
    float *cvec,*Opart,*lpart;
    int *cnt,*anyf;
    cudaGetSymbolAddress((void**)&qkv,    g_qkv);
    cudaGetSymbolAddress((void**)&curR,   g_curR);
    cudaGetSymbolAddress((void**)&Opart,  g_Opart);
    cudaGetSymbolAddress((void**)&lpart,  g_lpart);
    cudaGetSymbolAddress((void**)&wqkvr,  g_wqkvr);
    cudaGetSymbolAddress((void**)&twr,    g_twr);
    cudaGetSymbolAddress((void**)&w2r,    g_w2r);
    cudaGetSymbolAddress((void**)&wdr,    g_wdr);
    cudaGetSymbolAddress((void**)&w1cr,   g_w1cr);
    cudaGetSymbolAddress((void**)&cvec,   g_cvec);
    cudaGetSymbolAddress((void**)&cnt,    g_cnt);
    cudaGetSymbolAddress((void**)&anyf,   g_any);

    cudaFuncSetAttribute(qkv_gemm,   cudaFuncAttributeMaxDynamicSharedMemorySize, QKV_SMEM_BYTES);
    cudaFuncSetAttribute(flash_attn, cudaFuncAttributeMaxDynamicSharedMemorySize, FL_SMEM_BYTES);
    cudaFuncSetAttribute(rounds_all, cudaFuncAttributeMaxDynamicSharedMemorySize, RALL_SMEM_BYTES);

    prep_all<<<(PREP_ITEMS + 255)/256, 256>>>(
        wq, wk, wv, tw, w2, w1, tb, ab,
        wqkvr, twr, w2r, wdr, w1cr, cvec, cnt, anyf);

    qkv_gemm<<<dim3(3, MTOK/128), 256, QKV_SMEM_BYTES>>>(x, wqkvr, qkv);

    flash_attn<<<dim3(SEQ/128, BATCH, 2), 256, FL_SMEM_BYTES>>>(
        qkv, qkv + (size_t)MTOK*DHEAD, qkv + 2*(size_t)MTOK*DHEAD, Opart, lpart);

    flash_combine<<<MTOK*DHEAD/4/256, 256>>>(Opart, lpart, cur, curR);

    rounds_all<<<MTOK/128, 256, RALL_SMEM_BYTES>>>(
        cur, curR, twr, wdr, w1cr, w2r, cvec, b1, b2, gw, gb, cnt, anyf);
}

// round 14
// speedup vs baseline: 1.0419x; 1.0419x over previous
#include <cuda_runtime.h>
#include <cuda_fp16.h>
#include <math.h>
#include <stdint.h>

#define BATCH   8
#define SEQ     2048
#define DMODEL  1024
#define DHEAD   128
#define MTOK    (BATCH*SEQ)          // 16384
#define NROUNDS 3
#define SCALE_F 0.08838834764831843f // 1/sqrt(128)
#define LOG2E_F 1.4426950408889634f
#define SLG_F   (SCALE_F*LOG2E_F)
#define POFF_F  6.0f                 // constant exponent offset (cancels via l)

// ---------------- device scratch (no runtime allocation allowed) -------------
__device__ __align__(256) __half g_qkv[3*MTOK*DHEAD];         // q,k,v fp16
__device__ __align__(256) __half g_curR[MTOK*DHEAD];          // fp16 copy of cur
__device__ __align__(256) __half g_wqkvr[3*DHEAD*DMODEL];
__device__ __align__(256) __half g_twr[DHEAD*DHEAD];
__device__ __align__(256) __half g_w2r[DHEAD*DHEAD];
__device__ __align__(256) __half g_wdr[DHEAD*DHEAD];
__device__ __align__(256) __half g_w1cr[DHEAD*DHEAD];
__device__ float g_cvec[DHEAD];
__device__ int   g_cnt[NROUNDS];
__device__ int   g_any[NROUNDS];

// ---------------- PTX helpers -------------------------------------------------
__device__ __forceinline__ uint32_t s2u(const void* p) {
    uint32_t a;
    asm("{ .reg .u64 t; cvta.to.shared.u64 t, %1; cvt.u32.u64 %0, t; }" : "=r"(a) : "l"(p));
    return a;
}
__device__ __forceinline__ void cp_async16(uint32_t dst, const void* src) {
    asm volatile("cp.async.cg.shared.global [%0], [%1], 16;" :: "r"(dst), "l"(src) : "memory");
}
#define CP_COMMIT() asm volatile("cp.async.commit_group;" ::: "memory")
#define CP_WAIT(N)  asm volatile("cp.async.wait_group %0;" :: "n"(N) : "memory")
#define U32(p) (*reinterpret_cast<const uint32_t*>(p))

__device__ __forceinline__ uint32_t pk(float lo, float hi) {
    __half2 h = __floats2half2_rn(lo, hi);
    return *reinterpret_cast<uint32_t*>(&h);
}
__device__ __forceinline__ float ex2f(float x) {
    float y;
    asm("ex2.approx.ftz.f32 %0, %1;" : "=f"(y) : "f"(x));
    return y;
}

__device__ __forceinline__ void mma_f16(
    float& c0, float& c1, float& c2, float& c3,
    uint32_t a0, uint32_t a1, uint32_t a2, uint32_t a3,
    uint32_t b0, uint32_t b1)
{
    asm volatile(
        "mma.sync.aligned.m16n8k16.row.col.f32.f16.f16.f32 "
        "{%0,%1,%2,%3}, {%4,%5,%6,%7}, {%8,%9}, {%0,%1,%2,%3};"
        : "+f"(c0), "+f"(c1), "+f"(c2), "+f"(c3)
        : "r"(a0), "r"(a1), "r"(a2), "r"(a3), "r"(b0), "r"(b1));
}

__device__ __forceinline__ void ldsm4(uint32_t& d0, uint32_t& d1, uint32_t& d2,
                                      uint32_t& d3, uint32_t addr)
{
    asm volatile("ldmatrix.sync.aligned.m8n8.x4.shared.b16 {%0,%1,%2,%3}, [%4];"
        : "=r"(d0), "=r"(d1), "=r"(d2), "=r"(d3) : "r"(addr));
}
__device__ __forceinline__ void ldsm4t(uint32_t& d0, uint32_t& d1, uint32_t& d2,
                                       uint32_t& d3, uint32_t addr)
{
    asm volatile("ldmatrix.sync.aligned.m8n8.x4.trans.shared.b16 {%0,%1,%2,%3}, [%4];"
        : "=r"(d0), "=r"(d1), "=r"(d2), "=r"(d3) : "r"(addr));
}

// ---------------- QKV GEMM (fp16 mma, fp32 x converted in-kernel) -------------
#define QSA 40
#define QTILE_H (128*QSA)
#define QSTG_H (2*QTILE_H)
#define QKV_SMEM_BYTES (2*QSTG_H*2)   // 40960

__global__ __launch_bounds__(256) void qkv_gemm(
    const float* __restrict__ X, const __half* __restrict__ W,
    __half* __restrict__ out)
{
    extern __shared__ char smraw[];
    __half* smh = (__half*)smraw;
    const uint32_t sm_u = s2u(smh);
    const int z = blockIdx.x;
    const __half* B = W + (size_t)z*DHEAD*DMODEL;
    __half* C = out + (size_t)z*MTOK*DHEAD;
    const int tid = threadIdx.x, lane = tid & 31, warp = tid >> 5;
    const int wm = (warp >> 1) * 32, wn = (warp & 1) * 64;
    const int m0 = blockIdx.y * 128;
    const int lrow = tid >> 3, lc4 = (tid & 7) * 4;
    const int brow = tid >> 2, bc8 = (tid & 3) * 8;
    const int g = lane >> 2, t4 = lane & 3;
    const int nK = DMODEL >> 5;   // 32

    float4 areg[4];
    {
        const float* Ag = X + (size_t)m0*DMODEL + lc4;
        #pragma unroll
        for (int it = 0; it < 4; it++)
            areg[it] = *reinterpret_cast<const float4*>(Ag + (size_t)(lrow+it*32)*DMODEL);
        #pragma unroll
        for (int itb = 0; itb < 2; itb++)
            cp_async16(sm_u + (uint32_t)(QTILE_H + (brow+itb*64)*QSA + bc8)*2u,
                       B + (size_t)(brow+itb*64)*DMODEL + bc8);
        CP_COMMIT();
        #pragma unroll
        for (int it = 0; it < 4; it++) {
            float4 v = areg[it];
            uint2 h2 = make_uint2(pk(v.x, v.y), pk(v.z, v.w));
            *reinterpret_cast<uint2*>(&smh[(lrow+it*32)*QSA + lc4]) = h2;
        }
    }

    float acc[2][8][4];
    #pragma unroll
    for (int mi = 0; mi < 2; mi++)
        #pragma unroll
        for (int ni = 0; ni < 8; ni++)
            #pragma unroll
            for (int j = 0; j < 4; j++) acc[mi][ni][j] = 0.f;

    for (int kt = 0; kt < nK; kt++) {
        const int cs = kt & 1;
        if (kt + 1 < nK) {
            const int ko = (kt+1)*32;
            const float* Ag = X + (size_t)m0*DMODEL + ko + lc4;
            #pragma unroll
            for (int it = 0; it < 4; it++)
                areg[it] = *reinterpret_cast<const float4*>(Ag + (size_t)(lrow+it*32)*DMODEL);
            const int ns = cs ^ 1;
            #pragma unroll
            for (int itb = 0; itb < 2; itb++)
                cp_async16(sm_u + (uint32_t)(ns*QSTG_H + QTILE_H + (brow+itb*64)*QSA + bc8)*2u,
                           B + (size_t)(brow+itb*64)*DMODEL + ko + bc8);
            CP_COMMIT();
            CP_WAIT(1);
        } else {
            CP_WAIT(0);
        }
        __syncthreads();

        const __half* Ash = smh + cs*QSTG_H;
        const __half* Bsh = Ash + QTILE_H;
        #pragma unroll
        for (int kk = 0; kk < 2; kk++) {
            const int k0 = kk*16 + 2*t4;
            uint32_t a[2][4];
            #pragma unroll
            for (int mi = 0; mi < 2; mi++) {
                const __half* ap = Ash + (wm + mi*16 + g)*QSA + k0;
                a[mi][0] = U32(ap);
                a[mi][1] = U32(ap + 8*QSA);
                a[mi][2] = U32(ap + 8);
                a[mi][3] = U32(ap + 8*QSA + 8);
            }
            #pragma unroll
            for (int ni = 0; ni < 8; ni++) {
                const __half* bp = Bsh + (wn + ni*8 + g)*QSA + k0;
                uint32_t b0 = U32(bp), b1 = U32(bp + 8);
                #pragma unroll
                for (int mi = 0; mi < 2; mi++)
                    mma_f16(acc[mi][ni][0], acc[mi][ni][1], acc[mi][ni][2], acc[mi][ni][3],
                            a[mi][0], a[mi][1], a[mi][2], a[mi][3], b0, b1);
            }
        }
        if (kt + 1 < nK) {
            const int ns = cs ^ 1;
            __half* Ad = smh + ns*QSTG_H;
            #pragma unroll
            for (int it = 0; it < 4; it++) {
                float4 v = areg[it];
                uint2 h2 = make_uint2(pk(v.x, v.y), pk(v.z, v.w));
                *reinterpret_cast<uint2*>(&Ad[(lrow+it*32)*QSA + lc4]) = h2;
            }
        }
        __syncthreads();
    }

    #pragma unroll
    for (int mi = 0; mi < 2; mi++) {
        const int rA = m0 + wm + mi*16 + g, rB = rA + 8;
        #pragma unroll
        for (int ni = 0; ni < 8; ni++) {
            const int c0 = wn + ni*8 + 2*t4;
            *reinterpret_cast<__half2*>(C + (size_t)rA*DHEAD + c0) =
                __floats2half2_rn(acc[mi][ni][0], acc[mi][ni][1]);
            *reinterpret_cast<__half2*>(C + (size_t)rB*DHEAD + c0) =
                __floats2half2_rn(acc[mi][ni][2], acc[mi][ni][3]);
        }
    }
}

// ---------------- flash attention: 128 thr / 64 Q rows per CTA ----------------
// grid (SEQ/64, BATCH) = 256 CTAs; 2-3 co-resident per SM (no reg cap).
// Per-warp math identical to R12 (bitwise same results per row).
#define SKV 136
#define FH_K 0
#define FH_V (2*64*SKV)
#define FL_SMEM_BYTES ((FH_V + 2*64*SKV)*2)   // 69632

__global__ __launch_bounds__(128) void flash_attn(
    const __half* __restrict__ q, const __half* __restrict__ k,
    const __half* __restrict__ v, float* __restrict__ outc,
    __half* __restrict__ outR)
{
    extern __shared__ char smraw[];
    __half* smh = (__half*)smraw;
    const uint32_t sm_u = s2u(smh);
    const int b   = blockIdx.y;
    const int qb  = blockIdx.x * 64;
    const int tid = threadIdx.x, lane = tid & 31, warp = tid >> 5;   // warp 0..3
    const int g   = lane >> 2, t4 = lane & 3;

    const __half* qB = q + ((size_t)b*SEQ + qb)*DHEAD;
    const __half* kB = k + (size_t)b*SEQ*DHEAD;
    const __half* vB = v + (size_t)b*SEQ*DHEAD;

    // KV tile loads with 128 threads: row kc + it*8 (8 iters), col kf
    const int kc = tid >> 4;          // 0..7
    const int kf = (tid & 15) * 8;

    const int krow = (lane >> 4)*8 + (lane & 7);
    const int kcol = ((lane >> 3) & 1) * 8;

    uint32_t qa[8][4];
    {
        const __half* q0 = qB + (size_t)(warp*16 + g)*DHEAD;
        const __half* q8 = q0 + 8*DHEAD;
        #pragma unroll
        for (int ks = 0; ks < 8; ks++) {
            const int o = ks*16 + 2*t4;
            qa[ks][0] = U32(q0 + o);
            qa[ks][1] = U32(q8 + o);
            qa[ks][2] = U32(q0 + o + 8);
            qa[ks][3] = U32(q8 + o + 8);
        }
    }

    float oacc[16][4];
    #pragma unroll
    for (int ni = 0; ni < 16; ni++)
        #pragma unroll
        for (int j = 0; j < 4; j++) oacc[ni][j] = 0.f;
    float l0 = 0.f, l1 = 0.f;

    {
        #pragma unroll
        for (int it = 0; it < 8; it++) {
            cp_async16(sm_u + (uint32_t)(FH_K + (kc + it*8)*SKV + kf)*2u,
                       kB + (size_t)(kc + it*8)*DHEAD + kf);
            cp_async16(sm_u + (uint32_t)(FH_V + (kc + it*8)*SKV + kf)*2u,
                       vB + (size_t)(kc + it*8)*DHEAD + kf);
        }
        CP_COMMIT();
    }

    const int nTiles = SEQ / 64;  // 32
    for (int t = 0; t < nTiles; t++) {
        const int cs = t & 1;
        if (t + 1 < nTiles) {
            const int ns = cs ^ 1;
            const int kv1 = (t+1) * 64;
            #pragma unroll
            for (int it = 0; it < 8; it++) {
                cp_async16(sm_u + (uint32_t)(FH_K + ns*64*SKV + (kc + it*8)*SKV + kf)*2u,
                           kB + (size_t)(kv1 + kc + it*8)*DHEAD + kf);
                cp_async16(sm_u + (uint32_t)(FH_V + ns*64*SKV + (kc + it*8)*SKV + kf)*2u,
                           vB + (size_t)(kv1 + kc + it*8)*DHEAD + kf);
            }
            CP_COMMIT();
            CP_WAIT(1);
        } else {
            CP_WAIT(0);
        }
        __syncthreads();

        const uint32_t kb0 = sm_u + (uint32_t)(FH_K + cs*64*SKV + krow*SKV + kcol)*2u;
        const uint32_t vb0 = sm_u + (uint32_t)(FH_V + cs*64*SKV + lane*SKV)*2u;

        float sacc[8][4];
        #pragma unroll
        for (int ni = 0; ni < 8; ni++)
            #pragma unroll
            for (int j = 0; j < 4; j++) sacc[ni][j] = 0.f;
        #pragma unroll
        for (int ks = 0; ks < 8; ks++) {
            #pragma unroll
            for (int nj = 0; nj < 4; nj++) {
                uint32_t b0, b1, b2, b3;
                ldsm4(b0, b1, b2, b3, kb0 + (uint32_t)(nj*16*SKV + ks*16)*2u);
                mma_f16(sacc[2*nj][0], sacc[2*nj][1], sacc[2*nj][2], sacc[2*nj][3],
                        qa[ks][0], qa[ks][1], qa[ks][2], qa[ks][3], b0, b1);
                mma_f16(sacc[2*nj+1][0], sacc[2*nj+1][1], sacc[2*nj+1][2], sacc[2*nj+1][3],
                        qa[ks][0], qa[ks][1], qa[ks][2], qa[ks][3], b2, b3);
            }
        }

        // fixed-base softmax: P = exp2(s*scale*log2e - C); C cancels via l
        float rs0 = 0.f, rs1 = 0.f;
        uint32_t pa[4][4];
        #pragma unroll
        for (int j = 0; j < 4; j++) {
            const int n0i = 2*j, n1i = 2*j + 1;
            float p00 = ex2f(fmaf(sacc[n0i][0], SLG_F, -POFF_F));
            float p01 = ex2f(fmaf(sacc[n0i][1], SLG_F, -POFF_F));
            float p02 = ex2f(fmaf(sacc[n0i][2], SLG_F, -POFF_F));
            float p03 = ex2f(fmaf(sacc[n0i][3], SLG_F, -POFF_F));
            float p10 = ex2f(fmaf(sacc[n1i][0], SLG_F, -POFF_F));
            float p11 = ex2f(fmaf(sacc[n1i][1], SLG_F, -POFF_F));
            float p12 = ex2f(fmaf(sacc[n1i][2], SLG_F, -POFF_F));
            float p13 = ex2f(fmaf(sacc[n1i][3], SLG_F, -POFF_F));
            rs0 += p00 + p01 + p10 + p11;
            rs1 += p02 + p03 + p12 + p13;
            pa[j][0] = pk(p00, p01);
            pa[j][1] = pk(p02, p03);
            pa[j][2] = pk(p10, p11);
            pa[j][3] = pk(p12, p13);
        }
        rs0 += __shfl_xor_sync(0xffffffffu, rs0, 1);
        rs0 += __shfl_xor_sync(0xffffffffu, rs0, 2);
        rs1 += __shfl_xor_sync(0xffffffffu, rs1, 1);
        rs1 += __shfl_xor_sync(0xffffffffu, rs1, 2);
        l0 += rs0;
        l1 += rs1;

        #pragma unroll
        for (int jp = 0; jp < 2; jp++) {
            const uint32_t ab = vb0 + (uint32_t)(jp*32*SKV)*2u;
            #pragma unroll
            for (int ni = 0; ni < 16; ni++) {
                uint32_t b0, b1, b2, b3;
                ldsm4t(b0, b1, b2, b3, ab + ni*16);
                mma_f16(oacc[ni][0], oacc[ni][1], oacc[ni][2], oacc[ni][3],
                        pa[2*jp][0], pa[2*jp][1], pa[2*jp][2], pa[2*jp][3], b0, b1);
                mma_f16(oacc[ni][0], oacc[ni][1], oacc[ni][2], oacc[ni][3],
                        pa[2*jp+1][0], pa[2*jp+1][1], pa[2*jp+1][2], pa[2*jp+1][3], b2, b3);
            }
        }
        __syncthreads();
    }

    const float inv0 = 1.f / l0, inv1 = 1.f / l1;
    const size_t rowA = (size_t)b*SEQ + qb + warp*16 + g;
    const size_t rowB = rowA + 8;
    #pragma unroll
    for (int ni = 0; ni < 16; ni++) {
        const int c0 = ni*8 + 2*t4;
        float2 v0, v1;
        v0.x = oacc[ni][0]*inv0; v0.y = oacc[ni][1]*inv0;
        v1.x = oacc[ni][2]*inv1; v1.y = oacc[ni][3]*inv1;
        *reinterpret_cast<float2*>(outc + rowA*DHEAD + c0) = v0;
        *reinterpret_cast<float2*>(outc + rowB*DHEAD + c0) = v1;
        *reinterpret_cast<__half2*>(outR + rowA*DHEAD + c0) = __floats2half2_rn(v0.x, v0.y);
        *reinterpret_cast<__half2*>(outR + rowB*DHEAD + c0) = __floats2half2_rn(v1.x, v1.y);
    }
}

// ---------------- persistent merged rounds kernel (fp16, 256 thr, ldmatrix) ---
#define HSMS 136
#define RB_T0   0
#define RB_T1   34816
#define RB_T2   69632
#define RB_T3   104448
#define RB_T4   139264
#define RB_RED  174080
#define RB_ACT  176128
#define RALL_SMEM_BYTES (RB_ACT + 128*4)   // 176640
#define ZFS 132

__device__ __forceinline__ void load_tile128h(uint32_t sdst_bytes,
                                              const __half* __restrict__ src, int tid)
{
    const int row = tid >> 4, c8 = (tid & 15) * 8;
    #pragma unroll
    for (int it = 0; it < 8; it++)
        cp_async16(sdst_bytes + (uint32_t)((row + it*16)*HSMS + c8)*2u,
                   src + (size_t)(row + it*16)*128 + c8);
}

__device__ __forceinline__ void mma_128x128h(uint32_t aAddr, uint32_t bAddr,
                                             float acc[2][8][4])
{
    #pragma unroll
    for (int ks = 0; ks < 8; ks++) {
        uint32_t a[2][4];
        #pragma unroll
        for (int mi = 0; mi < 2; mi++)
            ldsm4(a[mi][0], a[mi][1], a[mi][2], a[mi][3],
                  aAddr + (uint32_t)(mi*16*HSMS + ks*16)*2u);
        #pragma unroll
        for (int nj = 0; nj < 4; nj++) {
            uint32_t b0, b1, b2, b3;
            ldsm4(b0, b1, b2, b3, bAddr + (uint32_t)(nj*16*HSMS + ks*16)*2u);
            #pragma unroll
            for (int mi = 0; mi < 2; mi++) {
                mma_f16(acc[mi][2*nj][0], acc[mi][2*nj][1], acc[mi][2*nj][2], acc[mi][2*nj][3],
                        a[mi][0], a[mi][1], a[mi][2], a[mi][3], b0, b1);
                mma_f16(acc[mi][2*nj+1][0], acc[mi][2*nj+1][1], acc[mi][2*nj+1][2], acc[mi][2*nj+1][3],
                        a[mi][0], a[mi][1], a[mi][2], a[mi][3], b2, b3);
            }
        }
    }
}

#define ZERO_ACC(acc) { \
    _Pragma("unroll") for (int mi = 0; mi < 2; mi++) \
        _Pragma("unroll") for (int ni = 0; ni < 8; ni++) \
            _Pragma("unroll") for (int j = 0; j < 4; j++) acc[mi][ni][j] = 0.f; }

__global__ __launch_bounds__(256) void rounds_all(
    float* __restrict__ cur, const __half* __restrict__ curR,
    const __half* __restrict__ tw, const __half* __restrict__ wd,
    const __half* __restrict__ w1c, const __half* __restrict__ w2,
    const float* __restrict__ cvec, const float* __restrict__ b1,
    const float* __restrict__ b2, const float* __restrict__ gw,
    const float* __restrict__ gb,
    int* __restrict__ cnt, int* __restrict__ anyf)
{
    extern __shared__ char smraw[];
    __half* smh = (__half*)smraw;
    const uint32_t sm_u = s2u(smraw);
    float* ZF  = reinterpret_cast<float*>(smraw + RB_T1);
    float* red = reinterpret_cast<float*>(smraw + RB_RED);
    int* s_act = reinterpret_cast<int*>(smraw + RB_ACT);
    __shared__ int s_flag, s_any;
    const int tid = threadIdx.x, lane = tid & 31, warp = tid >> 5;
    const int wm = (warp >> 1) * 32, wn = (warp & 1) * 64;
    const int g = lane >> 2, t4 = lane & 3;
    const int m0 = blockIdx.x * 128;

    const uint32_t aOff = (uint32_t)(((wm + (lane & 7) + 8*((lane >> 3) & 1))*HSMS
                                      + (lane >> 4)*8) * 2);
    const uint32_t bOff = (uint32_t)(((wn + (lane >> 4)*8 + (lane & 7))*HSMS
                                      + ((lane >> 3) & 1)*8) * 2);

    load_tile128h(sm_u + RB_T0, curR + (size_t)m0*128, tid);
    load_tile128h(sm_u + RB_T1, tw, tid);
    load_tile128h(sm_u + RB_T2, wd, tid);
    load_tile128h(sm_u + RB_T3, w1c, tid);
    load_tile128h(sm_u + RB_T4, w2, tid);
    CP_COMMIT(); CP_WAIT(0);
    if (tid < 128) s_act[tid] = 1;
    if (tid == 0) { s_flag = 1; s_any = 0; }
    __syncthreads();

    float acc[2][8][4];

    ZERO_ACC(acc);
    mma_128x128h(sm_u + RB_T0 + aOff, sm_u + RB_T1 + bOff, acc);
    __syncthreads();
    {
        __half* Ps = smh + RB_T1/2;
        #pragma unroll
        for (int mi = 0; mi < 2; mi++) {
            const int rA = wm + mi*16 + g, rB = rA + 8;
            #pragma unroll
            for (int ni = 0; ni < 8; ni++) {
                const int c0 = wn + ni*8 + 2*t4;
                *reinterpret_cast<__half2*>(&Ps[rA*HSMS + c0]) =
                    __floats2half2_rn(acc[mi][ni][0], acc[mi][ni][1]);
                *reinterpret_cast<__half2*>(&Ps[rB*HSMS + c0]) =
                    __floats2half2_rn(acc[mi][ni][2], acc[mi][ni][3]);
            }
        }
    }
    __syncthreads();
    ZERO_ACC(acc);
    mma_128x128h(sm_u + RB_T1 + aOff, sm_u + RB_T2 + bOff, acc);
    __syncthreads();
    {
        #pragma unroll
        for (int mi = 0; mi < 2; mi++) {
            const int rA = wm + mi*16 + g, rB = rA + 8;
            #pragma unroll
            for (int ni = 0; ni < 8; ni++) {
                const int c0 = wn + ni*8 + 2*t4;
                float2 v0, v1;
                v0.x = acc[mi][ni][0]; v0.y = acc[mi][ni][1];
                v1.x = acc[mi][ni][2]; v1.y = acc[mi][ni][3];
                *reinterpret_cast<float2*>(&ZF[rA*ZFS + c0]) = v0;
                *reinterpret_cast<float2*>(&ZF[rB*ZFS + c0]) = v1;
            }
        }
    }
    __syncthreads();

    for (int r = 0; r < NROUNDS; r++) {
        ZERO_ACC(acc);
        mma_128x128h(sm_u + RB_T0 + aOff, sm_u + RB_T3 + bOff, acc);
        __syncthreads();

        float amr[4];
        #pragma unroll
        for (int mi = 0; mi < 2; mi++) {
            const int rA = wm + mi*16 + g, rB = rA + 8;
            const float amA = s_act[rA] ? 1.f : 0.f;
            const float amB = s_act[rB] ? 1.f : 0.f;
            amr[mi*2] = amA; amr[mi*2+1] = amB;
            #pragma unroll
            for (int ni = 0; ni < 8; ni++) {
                const int c0 = wn + ni*8 + 2*t4;
                float2 zA = *reinterpret_cast<const float2*>(&ZF[rA*ZFS + c0]);
                float2 zB = *reinterpret_cast<const float2*>(&ZF[rB*ZFS + c0]);
                float2 cc = *reinterpret_cast<const float2*>(cvec + c0);
                float2 bb = *reinterpret_cast<const float2*>(b1 + c0);
                float h00 = fmaxf(fmaf(amA, acc[mi][ni][0] + zA.x + cc.x, bb.x), 0.f);
                float h01 = fmaxf(fmaf(amA, acc[mi][ni][1] + zA.y + cc.y, bb.y), 0.f);
                float h10 = fmaxf(fmaf(amB, acc[mi][ni][2] + zB.x + cc.x, bb.x), 0.f);
                float h11 = fmaxf(fmaf(amB, acc[mi][ni][3] + zB.y + cc.y, bb.y), 0.f);
                *reinterpret_cast<__half2*>(&smh[rA*HSMS + c0]) = __floats2half2_rn(h00, h01);
                *reinterpret_cast<__half2*>(&smh[rB*HSMS + c0]) = __floats2half2_rn(h10, h11);
            }
        }
        __syncthreads();

        ZERO_ACC(acc);
        mma_128x128h(sm_u + RB_T0 + aOff, sm_u + RB_T4 + bOff, acc);

        const int flg = s_flag;
        float d1[4] = {0,0,0,0}, nn[4] = {0,0,0,0};
        #pragma unroll
        for (int mi = 0; mi < 2; mi++) {
            const int rA = wm + mi*16 + g, rB = rA + 8;
            const float amA = amr[mi*2], amB = amr[mi*2+1];
            #pragma unroll
            for (int ni = 0; ni < 8; ni++) {
                const int c0 = wn + ni*8 + 2*t4;
                float2 cA = *reinterpret_cast<const float2*>(cur + (size_t)(m0+rA)*128 + c0);
                float2 cB = *reinterpret_cast<const float2*>(cur + (size_t)(m0+rB)*128 + c0);
                float2 bb = *reinterpret_cast<const float2*>(b2 + c0);
                float2 g1 = *reinterpret_cast<const float2*>(gw + c0);
                float2 g2 = *reinterpret_cast<const float2*>(gw + 128 + c0);
                float syA0 = acc[mi][ni][0] + bb.x, syA1 = acc[mi][ni][1] + bb.y;
                float syB0 = acc[mi][ni][2] + bb.x, syB1 = acc[mi][ni][3] + bb.y;
                float acA0 = cA.x * amA, acA1 = cA.y * amA;
                float acB0 = cB.x * amB, acB1 = cB.y * amB;
                d1[mi*2]   += acA0*g1.x + syA0*g2.x + acA1*g1.y + syA1*g2.y;
                d1[mi*2+1] += acB0*g1.x + syB0*g2.x + acB1*g1.y + syB1*g2.y;
                float dA0 = syA0-acA0, dA1 = syA1-acA1;
                float dB0 = syB0-acB0, dB1 = syB1-acB1;
                nn[mi*2]   += dA0*dA0 + dA1*dA1;
                nn[mi*2+1] += dB0*dB0 + dB1*dB1;
            }
        }
        #pragma unroll
        for (int j = 0; j < 4; j++) {
            d1[j] += __shfl_xor_sync(0xffffffffu, d1[j], 1);
            d1[j] += __shfl_xor_sync(0xffffffffu, d1[j], 2);
            nn[j] += __shfl_xor_sync(0xffffffffu, nn[j], 1);
            nn[j] += __shfl_xor_sync(0xffffffffu, nn[j], 2);
        }
        if (t4 == 0) {
            const int hf = (warp & 1) * 2;
            #pragma unroll
            for (int mi = 0; mi < 2; mi++) {
                const int rA = wm + mi*16 + g, rB = rA + 8;
                red[rA*4 + hf]     = d1[mi*2];
                red[rA*4 + hf + 1] = nn[mi*2];
                red[rB*4 + hf]     = d1[mi*2+1];
                red[rB*4 + hf + 1] = nn[mi*2+1];
            }
        }
        __syncthreads();

        const float gbv = gb[0];
        #pragma unroll
        for (int mi = 0; mi < 2; mi++) {
            const int rA = wm + mi*16 + g, rB = rA + 8;
            const float amA = amr[mi*2], amB = amr[mi*2+1];
            float gdA = red[rA*4+0] + red[rA*4+2] + gbv;
            float gdB = red[rB*4+0] + red[rB*4+2] + gbv;
            float n2A = red[rA*4+1] + red[rA*4+3];
            float n2B = red[rB*4+1] + red[rB*4+3];
            float gateA = 1.f / (1.f + expf(-gdA));
            float gateB = 1.f / (1.f + expf(-gdB));
            int stableA = (gateA * 0.1f * sqrtf(n2A)) < 0.1f;
            int stableB = (gateB * 0.1f * sqrtf(n2B)) < 0.1f;
            #pragma unroll
            for (int ni = 0; ni < 8; ni++) {
                const int c0 = wn + ni*8 + 2*t4;
                float2 cA = *reinterpret_cast<const float2*>(cur + (size_t)(m0+rA)*128 + c0);
                float2 cB = *reinterpret_cast<const float2*>(cur + (size_t)(m0+rB)*128 + c0);
                float2 bb = *reinterpret_cast<const float2*>(b2 + c0);
                float syA0 = acc[mi][ni][0] + bb.x, syA1 = acc[mi][ni][1] + bb.y;
                float syB0 = acc[mi][ni][2] + bb.x, syB1 = acc[mi][ni][3] + bb.y;
                float2 o0, o1;
                o0.x = cA.x; o0.y = cA.y; o1.x = cB.x; o1.y = cB.y;
                if (flg) {
                    o0.x += gateA * (syA0 - cA.x*amA) * 0.1f;
                    o0.y += gateA * (syA1 - cA.y*amA) * 0.1f;
                    o1.x += gateB * (syB0 - cB.x*amB) * 0.1f;
                    o1.y += gateB * (syB1 - cB.y*amB) * 0.1f;
                }
                *reinterpret_cast<float2*>(cur + (size_t)(m0+rA)*128 + c0) = o0;
                *reinterpret_cast<float2*>(cur + (size_t)(m0+rB)*128 + c0) = o1;
                *reinterpret_cast<__half2*>(&smh[rA*HSMS + c0]) = __floats2half2_rn(o0.x, o0.y);
                *reinterpret_cast<__half2*>(&smh[rB*HSMS + c0]) = __floats2half2_rn(o1.x, o1.y);
            }
            if ((warp & 1) == 0 && t4 == 0) {
                int actA = amA > 0.f, actB = amB > 0.f;
                int naA = actA && !stableA;
                int naB = actB && !stableB;
                if (flg) { s_act[rA] = naA; s_act[rB] = naB; }
                int effA = flg ? naA : actA;
                int effB = flg ? naB : actB;
                if (effA | effB) s_any = 1;
            }
        }
        __syncthreads();

        if (r + 1 < NROUNDS) {
            if (tid == 0) {
                if (s_any) atomicOr(&anyf[r], 1);
                __threadfence();
                atomicAdd(&cnt[r], 1);
                while (atomicAdd(&cnt[r], 0) < (int)gridDim.x) {}
                s_flag = (atomicOr(&anyf[r], 0) != 0) ? 1 : 0;
                s_any = 0;
            }
            __syncthreads();
        }
    }
}

// ---------------- single prep kernel (fp16 weight copies) ---------------------
__global__ void prep_all(
    const float* __restrict__ wq, const float* __restrict__ wk,
    const float* __restrict__ wv, const float* __restrict__ tw,
    const float* __restrict__ w2, const float* __restrict__ w1,
    const float* __restrict__ tb, const float* __restrict__ ab,
    __half* __restrict__ wqkvr, __half* __restrict__ twr,
    __half* __restrict__ w2r, __half* __restrict__ wdr,
    __half* __restrict__ w1cr, float* __restrict__ cvec,
    int* __restrict__ cnt, int* __restrict__ anyf)
{
    int idx = blockIdx.x * blockDim.x + threadIdx.x;
    const int WN4 = DHEAD*DMODEL/4;
    const int T4  = DHEAD*DHEAD/4;
    if (idx < 3*WN4) {
        const float* src = (idx < WN4) ? wq : (idx < 2*WN4 ? wk : wv);
        int off = (idx < WN4) ? idx : (idx < 2*WN4 ? idx - WN4 : idx - 2*WN4);
        float4 vv = reinterpret_cast<const float4*>(src)[off];
        reinterpret_cast<__half2*>(wqkvr)[2*idx]   = __floats2half2_rn(vv.x, vv.y);
        reinterpret_cast<__half2*>(wqkvr)[2*idx+1] = __floats2half2_rn(vv.z, vv.w);
        return;
    }
    idx -= 3*WN4;
    if (idx < T4) {
        float4 vv = reinterpret_cast<const float4*>(tw)[idx];
        reinterpret_cast<__half2*>(twr)[2*idx]   = __floats2half2_rn(vv.x, vv.y);
        reinterpret_cast<__half2*>(twr)[2*idx+1] = __floats2half2_rn(vv.z, vv.w);
        return;
    }
    idx -= T4;
    if (idx < T4) {
        float4 vv = reinterpret_cast<const float4*>(w2)[idx];
        reinterpret_cast<__half2*>(w2r)[2*idx]   = __floats2half2_rn(vv.x, vv.y);
        reinterpret_cast<__half2*>(w2r)[2*idx+1] = __floats2half2_rn(vv.z, vv.w);
        return;
    }
    idx -= T4;
    if (idx < DHEAD*DHEAD) {
        int j = idx >> 7, i = idx & 127;
        wdr[idx]  = __float2half_rn(w1[j*384 + i] - w1[j*384 + 128 + i]);
        w1cr[idx] = __float2half_rn(w1[j*384 + 256 + i]);
        return;
    }
    idx -= DHEAD*DHEAD;
    if (idx < DHEAD) {
        float s = 0.f;
        for (int i = 0; i < 128; i++)
            s += tb[i]*w1[idx*384 + i] + ab[i]*w1[idx*384 + 128 + i];
        cvec[idx] = s;
        return;
    }
    idx -= DHEAD;
    if (idx < NROUNDS) { cnt[idx] = 0; return; }
    idx -= NROUNDS;
    if (idx < NROUNDS) { anyf[idx] = 0; return; }
}
#define PREP_ITEMS (3*(DHEAD*DMODEL/4) + 2*(DHEAD*DHEAD/4) + DHEAD*DHEAD + DHEAD + 2*NROUNDS)

// ---------------- launch ------------------------------------------------------
extern "C" void kernel_launch(void* const* d_in, const int* in_sizes, int n_in,
                              void* d_out, int out_size)
{
    (void)in_sizes; (void)n_in; (void)out_size;
    const float* x  = (const float*)d_in[0];
    const float* wq = (const float*)d_in[1];
    const float* wk = (const float*)d_in[2];
    const float* wv = (const float*)d_in[3];
    const float* tw = (const float*)d_in[4];
    const float* tb = (const float*)d_in[5];
    const float* ab = (const float*)d_in[6];
    const float* w1 = (const float*)d_in[7];
    const float* b1 = (const float*)d_in[8];
    const float* w2 = (const float*)d_in[9];
    const float* b2 = (const float*)d_in[10];
    const float* gw = (const float*)d_in[11];
    const float* gb = (const float*)d_in[12];
    float* cur = (float*)d_out;

    __half *qkv,*curR,*wqkvr,*twr,*w2r,*wdr,*w1cr;
    float *cvec;
    int *cnt,*anyf;
    cudaGetSymbolAddress((void**)&qkv,    g_qkv);
    cudaGetSymbolAddress((void**)&curR,   g_curR);
    cudaGetSymbolAddress((void**)&wqkvr,  g_wqkvr);
    cudaGetSymbolAddress((void**)&twr,    g_twr);
    cudaGetSymbolAddress((void**)&w2r,    g_w2r);
    cudaGetSymbolAddress((void**)&wdr,    g_wdr);
    cudaGetSymbolAddress((void**)&w1cr,   g_w1cr);
    cudaGetSymbolAddress((void**)&cvec,   g_cvec);
    cudaGetSymbolAddress((void**)&cnt,    g_cnt);
    cudaGetSymbolAddress((void**)&anyf,   g_any);

    cudaFuncSetAttribute(qkv_gemm,   cudaFuncAttributeMaxDynamicSharedMemorySize, QKV_SMEM_BYTES);
    cudaFuncSetAttribute(flash_attn, cudaFuncAttributeMaxDynamicSharedMemorySize, FL_SMEM_BYTES);
    cudaFuncSetAttribute(rounds_all, cudaFuncAttributeMaxDynamicSharedMemorySize, RALL_SMEM_BYTES);

    prep_all<<<(PREP_ITEMS + 255)/256, 256>>>(
        wq, wk, wv, tw, w2, w1, tb, ab,
        wqkvr, twr, w2r, wdr, w1cr, cvec, cnt, anyf);

    qkv_gemm<<<dim3(3, MTOK/128), 256, QKV_SMEM_BYTES>>>(x, wqkvr, qkv);

    flash_attn<<<dim3(SEQ/64, BATCH), 128, FL_SMEM_BYTES>>>(
        qkv, qkv + (size_t)MTOK*DHEAD, qkv + 2*(size_t)MTOK*DHEAD, cur, curR);

    rounds_all<<<MTOK/128, 256, RALL_SMEM_BYTES>>>(
        cur, curR, twr, wdr, w1cr, w2r, cvec, b1, b2, gw, gb, cnt, anyf);
}

// round 15
// speedup vs baseline: 1.0423x; 1.0003x over previous
#include <cuda_runtime.h>
#include <cuda_fp16.h>
#include <math.h>
#include <stdint.h>

#define BATCH   8
#define SEQ     2048
#define DMODEL  1024
#define DHEAD   128
#define MTOK    (BATCH*SEQ)          // 16384
#define NROUNDS 3
#define SCALE_F 0.08838834764831843f // 1/sqrt(128)
#define LOG2E_F 1.4426950408889634f
#define SLG_F   (SCALE_F*LOG2E_F)
#define POFF_F  6.0f                 // constant exponent offset (cancels via l)

// ---------------- device scratch (no runtime allocation allowed) -------------
__device__ __align__(256) __half g_qkv[3*MTOK*DHEAD];         // q,k,v fp16
__device__ __align__(256) __half g_curR[MTOK*DHEAD];          // fp16 copy of cur
__device__ __align__(256) __half g_wqkvr[3*DHEAD*DMODEL];
__device__ __align__(256) __half g_twr[DHEAD*DHEAD];
__device__ __align__(256) __half g_w2r[DHEAD*DHEAD];
__device__ __align__(256) __half g_wdr[DHEAD*DHEAD];
__device__ __align__(256) __half g_w1cr[DHEAD*DHEAD];
__device__ float g_cvec[DHEAD];
__device__ int   g_cnt[NROUNDS];
__device__ int   g_any[NROUNDS];

// ---------------- PTX helpers -------------------------------------------------
__device__ __forceinline__ uint32_t s2u(const void* p) {
    uint32_t a;
    asm("{ .reg .u64 t; cvta.to.shared.u64 t, %1; cvt.u32.u64 %0, t; }" : "=r"(a) : "l"(p));
    return a;
}
__device__ __forceinline__ void cp_async16(uint32_t dst, const void* src) {
    asm volatile("cp.async.cg.shared.global [%0], [%1], 16;" :: "r"(dst), "l"(src) : "memory");
}
#define CP_COMMIT() asm volatile("cp.async.commit_group;" ::: "memory")
#define CP_WAIT(N)  asm volatile("cp.async.wait_group %0;" :: "n"(N) : "memory")
#define U32(p) (*reinterpret_cast<const uint32_t*>(p))

__device__ __forceinline__ uint32_t pk(float lo, float hi) {
    __half2 h = __floats2half2_rn(lo, hi);
    return *reinterpret_cast<uint32_t*>(&h);
}
__device__ __forceinline__ float ex2f(float x) {
    float y;
    asm("ex2.approx.ftz.f32 %0, %1;" : "=f"(y) : "f"(x));
    return y;
}

__device__ __forceinline__ void mma_f16(
    float& c0, float& c1, float& c2, float& c3,
    uint32_t a0, uint32_t a1, uint32_t a2, uint32_t a3,
    uint32_t b0, uint32_t b1)
{
    asm volatile(
        "mma.sync.aligned.m16n8k16.row.col.f32.f16.f16.f32 "
        "{%0,%1,%2,%3}, {%4,%5,%6,%7}, {%8,%9}, {%0,%1,%2,%3};"
        : "+f"(c0), "+f"(c1), "+f"(c2), "+f"(c3)
        : "r"(a0), "r"(a1), "r"(a2), "r"(a3), "r"(b0), "r"(b1));
}

__device__ __forceinline__ void ldsm4(uint32_t& d0, uint32_t& d1, uint32_t& d2,
                                      uint32_t& d3, uint32_t addr)
{
    asm volatile("ldmatrix.sync.aligned.m8n8.x4.shared.b16 {%0,%1,%2,%3}, [%4];"
        : "=r"(d0), "=r"(d1), "=r"(d2), "=r"(d3) : "r"(addr));
}
__device__ __forceinline__ void ldsm4t(uint32_t& d0, uint32_t& d1, uint32_t& d2,
                                       uint32_t& d3, uint32_t addr)
{
    asm volatile("ldmatrix.sync.aligned.m8n8.x4.trans.shared.b16 {%0,%1,%2,%3}, [%4];"
        : "=r"(d0), "=r"(d1), "=r"(d2), "=r"(d3) : "r"(addr));
}

// ---------------- QKV GEMM (fp16 mma, fp32 x converted in-kernel) -------------
#define QSA 40
#define QTILE_H (128*QSA)
#define QSTG_H (2*QTILE_H)
#define QKV_SMEM_BYTES (2*QSTG_H*2)   // 40960

__global__ __launch_bounds__(256) void qkv_gemm(
    const float* __restrict__ X, const __half* __restrict__ W,
    __half* __restrict__ out)
{
    extern __shared__ char smraw[];
    __half* smh = (__half*)smraw;
    const uint32_t sm_u = s2u(smh);
    const int z = blockIdx.x;
    const __half* B = W + (size_t)z*DHEAD*DMODEL;
    __half* C = out + (size_t)z*MTOK*DHEAD;
    const int tid = threadIdx.x, lane = tid & 31, warp = tid >> 5;
    const int wm = (warp >> 1) * 32, wn = (warp & 1) * 64;
    const int m0 = blockIdx.y * 128;
    const int lrow = tid >> 3, lc4 = (tid & 7) * 4;
    const int brow = tid >> 2, bc8 = (tid & 3) * 8;
    const int g = lane >> 2, t4 = lane & 3;
    const int nK = DMODEL >> 5;   // 32

    float4 areg[4];
    {
        const float* Ag = X + (size_t)m0*DMODEL + lc4;
        #pragma unroll
        for (int it = 0; it < 4; it++)
            areg[it] = *reinterpret_cast<const float4*>(Ag + (size_t)(lrow+it*32)*DMODEL);
        #pragma unroll
        for (int itb = 0; itb < 2; itb++)
            cp_async16(sm_u + (uint32_t)(QTILE_H + (brow+itb*64)*QSA + bc8)*2u,
                       B + (size_t)(brow+itb*64)*DMODEL + bc8);
        CP_COMMIT();
        #pragma unroll
        for (int it = 0; it < 4; it++) {
            float4 v = areg[it];
            uint2 h2 = make_uint2(pk(v.x, v.y), pk(v.z, v.w));
            *reinterpret_cast<uint2*>(&smh[(lrow+it*32)*QSA + lc4]) = h2;
        }
    }

    float acc[2][8][4];
    #pragma unroll
    for (int mi = 0; mi < 2; mi++)
        #pragma unroll
        for (int ni = 0; ni < 8; ni++)
            #pragma unroll
            for (int j = 0; j < 4; j++) acc[mi][ni][j] = 0.f;

    for (int kt = 0; kt < nK; kt++) {
        const int cs = kt & 1;
        if (kt + 1 < nK) {
            const int ko = (kt+1)*32;
            const float* Ag = X + (size_t)m0*DMODEL + ko + lc4;
            #pragma unroll
            for (int it = 0; it < 4; it++)
                areg[it] = *reinterpret_cast<const float4*>(Ag + (size_t)(lrow+it*32)*DMODEL);
            const int ns = cs ^ 1;
            #pragma unroll
            for (int itb = 0; itb < 2; itb++)
                cp_async16(sm_u + (uint32_t)(ns*QSTG_H + QTILE_H + (brow+itb*64)*QSA + bc8)*2u,
                           B + (size_t)(brow+itb*64)*DMODEL + ko + bc8);
            CP_COMMIT();
            CP_WAIT(1);
        } else {
            CP_WAIT(0);
        }
        __syncthreads();

        const __half* Ash = smh + cs*QSTG_H;
        const __half* Bsh = Ash + QTILE_H;
        #pragma unroll
        for (int kk = 0; kk < 2; kk++) {
            const int k0 = kk*16 + 2*t4;
            uint32_t a[2][4];
            #pragma unroll
            for (int mi = 0; mi < 2; mi++) {
                const __half* ap = Ash + (wm + mi*16 + g)*QSA + k0;
                a[mi][0] = U32(ap);
                a[mi][1] = U32(ap + 8*QSA);
                a[mi][2] = U32(ap + 8);
                a[mi][3] = U32(ap + 8*QSA + 8);
            }
            #pragma unroll
            for (int ni = 0; ni < 8; ni++) {
                const __half* bp = Bsh + (wn + ni*8 + g)*QSA + k0;
                uint32_t b0 = U32(bp), b1 = U32(bp + 8);
                #pragma unroll
                for (int mi = 0; mi < 2; mi++)
                    mma_f16(acc[mi][ni][0], acc[mi][ni][1], acc[mi][ni][2], acc[mi][ni][3],
                            a[mi][0], a[mi][1], a[mi][2], a[mi][3], b0, b1);
            }
        }
        if (kt + 1 < nK) {
            const int ns = cs ^ 1;
            __half* Ad = smh + ns*QSTG_H;
            #pragma unroll
            for (int it = 0; it < 4; it++) {
                float4 v = areg[it];
                uint2 h2 = make_uint2(pk(v.x, v.y), pk(v.z, v.w));
                *reinterpret_cast<uint2*>(&Ad[(lrow+it*32)*QSA + lc4]) = h2;
            }
        }
        __syncthreads();
    }

    #pragma unroll
    for (int mi = 0; mi < 2; mi++) {
        const int rA = m0 + wm + mi*16 + g, rB = rA + 8;
        #pragma unroll
        for (int ni = 0; ni < 8; ni++) {
            const int c0 = wn + ni*8 + 2*t4;
            *reinterpret_cast<__half2*>(C + (size_t)rA*DHEAD + c0) =
                __floats2half2_rn(acc[mi][ni][0], acc[mi][ni][1]);
            *reinterpret_cast<__half2*>(C + (size_t)rB*DHEAD + c0) =
                __floats2half2_rn(acc[mi][ni][2], acc[mi][ni][3]);
        }
    }
}

// ---------------- flash attention (R12 shape + pipelined PV) ------------------
// 256 thr / 128 Q rows per CTA; K double-buffered, V triple-buffered.
// PV of tile t-1 issues during softmax of tile t (fills the tensor bubble).
// oacc mma order identical to R12 -> bitwise identical output.
#define SKV 136
#define FH_K 0
#define FH_V (2*64*SKV)
#define FL_SMEM_BYTES ((2*64*SKV + 3*64*SKV)*2)   // 87040

#define PV_STEP(paX, vbX) { \
    _Pragma("unroll") \
    for (int jp = 0; jp < 2; jp++) { \
        const uint32_t ab = (vbX) + (uint32_t)(jp*32*SKV)*2u; \
        _Pragma("unroll") \
        for (int ni = 0; ni < 16; ni++) { \
            uint32_t b0, b1, b2, b3; \
            ldsm4t(b0, b1, b2, b3, ab + ni*16); \
            mma_f16(oacc[ni][0], oacc[ni][1], oacc[ni][2], oacc[ni][3], \
                    (paX)[2*jp][0], (paX)[2*jp][1], (paX)[2*jp][2], (paX)[2*jp][3], b0, b1); \
            mma_f16(oacc[ni][0], oacc[ni][1], oacc[ni][2], oacc[ni][3], \
                    (paX)[2*jp+1][0], (paX)[2*jp+1][1], (paX)[2*jp+1][2], (paX)[2*jp+1][3], b2, b3); \
        } \
    } }

__global__ __launch_bounds__(256) void flash_attn(
    const __half* __restrict__ q, const __half* __restrict__ k,
    const __half* __restrict__ v, float* __restrict__ outc,
    __half* __restrict__ outR)
{
    extern __shared__ char smraw[];
    const uint32_t sm_u = s2u(smraw);
    const int b   = blockIdx.y;
    const int qb  = blockIdx.x * 128;
    const int tid = threadIdx.x, lane = tid & 31, warp = tid >> 5;
    const int g   = lane >> 2, t4 = lane & 3;

    const __half* qB = q + ((size_t)b*SEQ + qb)*DHEAD;
    const __half* kB = k + (size_t)b*SEQ*DHEAD;
    const __half* vB = v + (size_t)b*SEQ*DHEAD;

    const int kc = tid >> 4;          // 0..15 (+16/iter, 4 iters)
    const int kf = (tid & 15) * 8;

    const int krow = (lane >> 4)*8 + (lane & 7);
    const int kcol = ((lane >> 3) & 1) * 8;

    uint32_t qa[8][4];
    {
        const __half* q0 = qB + (size_t)(warp*16 + g)*DHEAD;
        const __half* q8 = q0 + 8*DHEAD;
        #pragma unroll
        for (int ks = 0; ks < 8; ks++) {
            const int o = ks*16 + 2*t4;
            qa[ks][0] = U32(q0 + o);
            qa[ks][1] = U32(q8 + o);
            qa[ks][2] = U32(q0 + o + 8);
            qa[ks][3] = U32(q8 + o + 8);
        }
    }

    float oacc[16][4];
    #pragma unroll
    for (int ni = 0; ni < 16; ni++)
        #pragma unroll
        for (int j = 0; j < 4; j++) oacc[ni][j] = 0.f;
    float l0 = 0.f, l1 = 0.f;

    {
        #pragma unroll
        for (int it = 0; it < 4; it++) {
            cp_async16(sm_u + (uint32_t)(FH_K + (kc + it*16)*SKV + kf)*2u,
                       kB + (size_t)(kc + it*16)*DHEAD + kf);
            cp_async16(sm_u + (uint32_t)(FH_V + (kc + it*16)*SKV + kf)*2u,
                       vB + (size_t)(kc + it*16)*DHEAD + kf);
        }
        CP_COMMIT();
    }

    uint32_t paPrev[4][4];
    uint32_t vbPrev = 0;

    const int nTiles = SEQ / 64;  // 32
    for (int t = 0; t < nTiles; t++) {
        const int cs2 = t & 1;
        const int cs3 = t % 3;
        if (t + 1 < nTiles) {
            const int ns2 = (t+1) & 1;
            const int ns3 = (t+1) % 3;
            const int kv1 = (t+1) * 64;
            #pragma unroll
            for (int it = 0; it < 4; it++) {
                cp_async16(sm_u + (uint32_t)(FH_K + ns2*64*SKV + (kc + it*16)*SKV + kf)*2u,
                           kB + (size_t)(kv1 + kc + it*16)*DHEAD + kf);
                cp_async16(sm_u + (uint32_t)(FH_V + ns3*64*SKV + (kc + it*16)*SKV + kf)*2u,
                           vB + (size_t)(kv1 + kc + it*16)*DHEAD + kf);
            }
            CP_COMMIT();
            CP_WAIT(1);
        } else {
            CP_WAIT(0);
        }
        __syncthreads();

        const uint32_t kb0 = sm_u + (uint32_t)(FH_K + cs2*64*SKV + krow*SKV + kcol)*2u;
        const uint32_t vb0 = sm_u + (uint32_t)(FH_V + cs3*64*SKV + lane*SKV)*2u;

        // S = Q @ K^T
        float sacc[8][4];
        #pragma unroll
        for (int ni = 0; ni < 8; ni++)
            #pragma unroll
            for (int j = 0; j < 4; j++) sacc[ni][j] = 0.f;
        #pragma unroll
        for (int ks = 0; ks < 8; ks++) {
            #pragma unroll
            for (int nj = 0; nj < 4; nj++) {
                uint32_t b0, b1, b2, b3;
                ldsm4(b0, b1, b2, b3, kb0 + (uint32_t)(nj*16*SKV + ks*16)*2u);
                mma_f16(sacc[2*nj][0], sacc[2*nj][1], sacc[2*nj][2], sacc[2*nj][3],
                        qa[ks][0], qa[ks][1], qa[ks][2], qa[ks][3], b0, b1);
                mma_f16(sacc[2*nj+1][0], sacc[2*nj+1][1], sacc[2*nj+1][2], sacc[2*nj+1][3],
                        qa[ks][0], qa[ks][1], qa[ks][2], qa[ks][3], b2, b3);
            }
        }

        // PV of previous tile: independent of sacc -> overlaps softmax's
        // scoreboard wait on the QK mmas above.
        if (t > 0) PV_STEP(paPrev, vbPrev);

        // fixed-base softmax: P = exp2(s*scale*log2e - C); C cancels via l
        float rs0 = 0.f, rs1 = 0.f;
        uint32_t pa[4][4];
        #pragma unroll
        for (int j = 0; j < 4; j++) {
            const int n0i = 2*j, n1i = 2*j + 1;
            float p00 = ex2f(fmaf(sacc[n0i][0], SLG_F, -POFF_F));
            float p01 = ex2f(fmaf(sacc[n0i][1], SLG_F, -POFF_F));
            float p02 = ex2f(fmaf(sacc[n0i][2], SLG_F, -POFF_F));
            float p03 = ex2f(fmaf(sacc[n0i][3], SLG_F, -POFF_F));
            float p10 = ex2f(fmaf(sacc[n1i][0], SLG_F, -POFF_F));
            float p11 = ex2f(fmaf(sacc[n1i][1], SLG_F, -POFF_F));
            float p12 = ex2f(fmaf(sacc[n1i][2], SLG_F, -POFF_F));
            float p13 = ex2f(fmaf(sacc[n1i][3], SLG_F, -POFF_F));
            rs0 += p00 + p01 + p10 + p11;
            rs1 += p02 + p03 + p12 + p13;
            pa[j][0] = pk(p00, p01);
            pa[j][1] = pk(p02, p03);
            pa[j][2] = pk(p10, p11);
            pa[j][3] = pk(p12, p13);
        }
        rs0 += __shfl_xor_sync(0xffffffffu, rs0, 1);
        rs0 += __shfl_xor_sync(0xffffffffu, rs0, 2);
        rs1 += __shfl_xor_sync(0xffffffffu, rs1, 1);
        rs1 += __shfl_xor_sync(0xffffffffu, rs1, 2);
        l0 += rs0;
        l1 += rs1;

        #pragma unroll
        for (int j = 0; j < 4; j++) {
            paPrev[j][0] = pa[j][0]; paPrev[j][1] = pa[j][1];
            paPrev[j][2] = pa[j][2]; paPrev[j][3] = pa[j][3];
        }
        vbPrev = vb0;
        __syncthreads();
    }

    // drain: PV of the final tile (its V stage is no longer overwritten)
    PV_STEP(paPrev, vbPrev);

    const float inv0 = 1.f / l0, inv1 = 1.f / l1;
    const size_t rowA = (size_t)b*SEQ + qb + warp*16 + g;
    const size_t rowB = rowA + 8;
    #pragma unroll
    for (int ni = 0; ni < 16; ni++) {
        const int c0 = ni*8 + 2*t4;
        float2 v0, v1;
        v0.x = oacc[ni][0]*inv0; v0.y = oacc[ni][1]*inv0;
        v1.x = oacc[ni][2]*inv1; v1.y = oacc[ni][3]*inv1;
        *reinterpret_cast<float2*>(outc + rowA*DHEAD + c0) = v0;
        *reinterpret_cast<float2*>(outc + rowB*DHEAD + c0) = v1;
        *reinterpret_cast<__half2*>(outR + rowA*DHEAD + c0) = __floats2half2_rn(v0.x, v0.y);
        *reinterpret_cast<__half2*>(outR + rowB*DHEAD + c0) = __floats2half2_rn(v1.x, v1.y);
    }
}

// ---------------- persistent merged rounds kernel (fp16, 256 thr, ldmatrix) ---
#define HSMS 136
#define RB_T0   0
#define RB_T1   34816
#define RB_T2   69632
#define RB_T3   104448
#define RB_T4   139264
#define RB_RED  174080
#define RB_ACT  176128
#define RALL_SMEM_BYTES (RB_ACT + 128*4)   // 176640
#define ZFS 132

__device__ __forceinline__ void load_tile128h(uint32_t sdst_bytes,
                                              const __half* __restrict__ src, int tid)
{
    const int row = tid >> 4, c8 = (tid & 15) * 8;
    #pragma unroll
    for (int it = 0; it < 8; it++)
        cp_async16(sdst_bytes + (uint32_t)((row + it*16)*HSMS + c8)*2u,
                   src + (size_t)(row + it*16)*128 + c8);
}

__device__ __forceinline__ void mma_128x128h(uint32_t aAddr, uint32_t bAddr,
                                             float acc[2][8][4])
{
    #pragma unroll
    for (int ks = 0; ks < 8; ks++) {
        uint32_t a[2][4];
        #pragma unroll
        for (int mi = 0; mi < 2; mi++)
            ldsm4(a[mi][0], a[mi][1], a[mi][2], a[mi][3],
                  aAddr + (uint32_t)(mi*16*HSMS + ks*16)*2u);
        #pragma unroll
        for (int nj = 0; nj < 4; nj++) {
            uint32_t b0, b1, b2, b3;
            ldsm4(b0, b1, b2, b3, bAddr + (uint32_t)(nj*16*HSMS + ks*16)*2u);
            #pragma unroll
            for (int mi = 0; mi < 2; mi++) {
                mma_f16(acc[mi][2*nj][0], acc[mi][2*nj][1], acc[mi][2*nj][2], acc[mi][2*nj][3],
                        a[mi][0], a[mi][1], a[mi][2], a[mi][3], b0, b1);
                mma_f16(acc[mi][2*nj+1][0], acc[mi][2*nj+1][1], acc[mi][2*nj+1][2], acc[mi][2*nj+1][3],
                        a[mi][0], a[mi][1], a[mi][2], a[mi][3], b2, b3);
            }
        }
    }
}

#define ZERO_ACC(acc) { \
    _Pragma("unroll") for (int mi = 0; mi < 2; mi++) \
        _Pragma("unroll") for (int ni = 0; ni < 8; ni++) \
            _Pragma("unroll") for (int j = 0; j < 4; j++) acc[mi][ni][j] = 0.f; }

__global__ __launch_bounds__(256) void rounds_all(
    float* __restrict__ cur, const __half* __restrict__ curR,
    const __half* __restrict__ tw, const __half* __restrict__ wd,
    const __half* __restrict__ w1c, const __half* __restrict__ w2,
    const float* __restrict__ cvec, const float* __restrict__ b1,
    const float* __restrict__ b2, const float* __restrict__ gw,
    const float* __restrict__ gb,
    int* __restrict__ cnt, int* __restrict__ anyf)
{
    extern __shared__ char smraw[];
    __half* smh = (__half*)smraw;
    const uint32_t sm_u = s2u(smraw);
    float* ZF  = reinterpret_cast<float*>(smraw + RB_T1);
    float* red = reinterpret_cast<float*>(smraw + RB_RED);
    int* s_act = reinterpret_cast<int*>(smraw + RB_ACT);
    __shared__ int s_flag, s_any;
    const int tid = threadIdx.x, lane = tid & 31, warp = tid >> 5;
    const int wm = (warp >> 1) * 32, wn = (warp & 1) * 64;
    const int g = lane >> 2, t4 = lane & 3;
    const int m0 = blockIdx.x * 128;

    const uint32_t aOff = (uint32_t)(((wm + (lane & 7) + 8*((lane >> 3) & 1))*HSMS
                                      + (lane >> 4)*8) * 2);
    const uint32_t bOff = (uint32_t)(((wn + (lane >> 4)*8 + (lane & 7))*HSMS
                                      + ((lane >> 3) & 1)*8) * 2);

    load_tile128h(sm_u + RB_T0, curR + (size_t)m0*128, tid);
    load_tile128h(sm_u + RB_T1, tw, tid);
    load_tile128h(sm_u + RB_T2, wd, tid);
    load_tile128h(sm_u + RB_T3, w1c, tid);
    load_tile128h(sm_u + RB_T4, w2, tid);
    CP_COMMIT(); CP_WAIT(0);
    if (tid < 128) s_act[tid] = 1;
    if (tid == 0) { s_flag = 1; s_any = 0; }
    __syncthreads();

    float acc[2][8][4];

    ZERO_ACC(acc);
    mma_128x128h(sm_u + RB_T0 + aOff, sm_u + RB_T1 + bOff, acc);
    __syncthreads();
    {
        __half* Ps = smh + RB_T1/2;
        #pragma unroll
        for (int mi = 0; mi < 2; mi++) {
            const int rA = wm + mi*16 + g, rB = rA + 8;
            #pragma unroll
            for (int ni = 0; ni < 8; ni++) {
                const int c0 = wn + ni*8 + 2*t4;
                *reinterpret_cast<__half2*>(&Ps[rA*HSMS + c0]) =
                    __floats2half2_rn(acc[mi][ni][0], acc[mi][ni][1]);
                *reinterpret_cast<__half2*>(&Ps[rB*HSMS + c0]) =
                    __floats2half2_rn(acc[mi][ni][2], acc[mi][ni][3]);
            }
        }
    }
    __syncthreads();
    ZERO_ACC(acc);
    mma_128x128h(sm_u + RB_T1 + aOff, sm_u + RB_T2 + bOff, acc);
    __syncthreads();
    {
        #pragma unroll
        for (int mi = 0; mi < 2; mi++) {
            const int rA = wm + mi*16 + g, rB = rA + 8;
            #pragma unroll
            for (int ni = 0; ni < 8; ni++) {
                const int c0 = wn + ni*8 + 2*t4;
                float2 v0, v1;
                v0.x = acc[mi][ni][0]; v0.y = acc[mi][ni][1];
                v1.x = acc[mi][ni][2]; v1.y = acc[mi][ni][3];
                *reinterpret_cast<float2*>(&ZF[rA*ZFS + c0]) = v0;
                *reinterpret_cast<float2*>(&ZF[rB*ZFS + c0]) = v1;
            }
        }
    }
    __syncthreads();

    for (int r = 0; r < NROUNDS; r++) {
        ZERO_ACC(acc);
        mma_128x128h(sm_u + RB_T0 + aOff, sm_u + RB_T3 + bOff, acc);
        __syncthreads();

        float amr[4];
        #pragma unroll
        for (int mi = 0; mi < 2; mi++) {
            const int rA = wm + mi*16 + g, rB = rA + 8;
            const float amA = s_act[rA] ? 1.f : 0.f;
            const float amB = s_act[rB] ? 1.f : 0.f;
            amr[mi*2] = amA; amr[mi*2+1] = amB;
            #pragma unroll
            for (int ni = 0; ni < 8; ni++) {
                const int c0 = wn + ni*8 + 2*t4;
                float2 zA = *reinterpret_cast<const float2*>(&ZF[rA*ZFS + c0]);
                float2 zB = *reinterpret_cast<const float2*>(&ZF[rB*ZFS + c0]);
                float2 cc = *reinterpret_cast<const float2*>(cvec + c0);
                float2 bb = *reinterpret_cast<const float2*>(b1 + c0);
                float h00 = fmaxf(fmaf(amA, acc[mi][ni][0] + zA.x + cc.x, bb.x), 0.f);
                float h01 = fmaxf(fmaf(amA, acc[mi][ni][1] + zA.y + cc.y, bb.y), 0.f);
                float h10 = fmaxf(fmaf(amB, acc[mi][ni][2] + zB.x + cc.x, bb.x), 0.f);
                float h11 = fmaxf(fmaf(amB, acc[mi][ni][3] + zB.y + cc.y, bb.y), 0.f);
                *reinterpret_cast<__half2*>(&smh[rA*HSMS + c0]) = __floats2half2_rn(h00, h01);
                *reinterpret_cast<__half2*>(&smh[rB*HSMS + c0]) = __floats2half2_rn(h10, h11);
            }
        }
        __syncthreads();

        ZERO_ACC(acc);
        mma_128x128h(sm_u + RB_T0 + aOff, sm_u + RB_T4 + bOff, acc);

        const int flg = s_flag;
        float d1[4] = {0,0,0,0}, nn[4] = {0,0,0,0};
        #pragma unroll
        for (int mi = 0; mi < 2; mi++) {
            const int rA = wm + mi*16 + g, rB = rA + 8;
            const float amA = amr[mi*2], amB = amr[mi*2+1];
            #pragma unroll
            for (int ni = 0; ni < 8; ni++) {
                const int c0 = wn + ni*8 + 2*t4;
                float2 cA = *reinterpret_cast<const float2*>(cur + (size_t)(m0+rA)*128 + c0);
                float2 cB = *reinterpret_cast<const float2*>(cur + (size_t)(m0+rB)*128 + c0);
                float2 bb = *reinterpret_cast<const float2*>(b2 + c0);
                float2 g1 = *reinterpret_cast<const float2*>(gw + c0);
                float2 g2 = *reinterpret_cast<const float2*>(gw + 128 + c0);
                float syA0 = acc[mi][ni][0] + bb.x, syA1 = acc[mi][ni][1] + bb.y;
                float syB0 = acc[mi][ni][2] + bb.x, syB1 = acc[mi][ni][3] + bb.y;
                float acA0 = cA.x * amA, acA1 = cA.y * amA;
                float acB0 = cB.x * amB, acB1 = cB.y * amB;
                d1[mi*2]   += acA0*g1.x + syA0*g2.x + acA1*g1.y + syA1*g2.y;
                d1[mi*2+1] += acB0*g1.x + syB0*g2.x + acB1*g1.y + syB1*g2.y;
                float dA0 = syA0-acA0, dA1 = syA1-acA1;
                float dB0 = syB0-acB0, dB1 = syB1-acB1;
                nn[mi*2]   += dA0*dA0 + dA1*dA1;
                nn[mi*2+1] += dB0*dB0 + dB1*dB1;
            }
        }
        #pragma unroll
        for (int j = 0; j < 4; j++) {
            d1[j] += __shfl_xor_sync(0xffffffffu, d1[j], 1);
            d1[j] += __shfl_xor_sync(0xffffffffu, d1[j], 2);
            nn[j] += __shfl_xor_sync(0xffffffffu, nn[j], 1);
            nn[j] += __shfl_xor_sync(0xffffffffu, nn[j], 2);
        }
        if (t4 == 0) {
            const int hf = (warp & 1) * 2;
            #pragma unroll
            for (int mi = 0; mi < 2; mi++) {
                const int rA = wm + mi*16 + g, rB = rA + 8;
                red[rA*4 + hf]     = d1[mi*2];
                red[rA*4 + hf + 1] = nn[mi*2];
                red[rB*4 + hf]     = d1[mi*2+1];
                red[rB*4 + hf + 1] = nn[mi*2+1];
            }
        }
        __syncthreads();

        const float gbv = gb[0];
        #pragma unroll
        for (int mi = 0; mi < 2; mi++) {
            const int rA = wm + mi*16 + g, rB = rA + 8;
            const float amA = amr[mi*2], amB = amr[mi*2+1];
            float gdA = red[rA*4+0] + red[rA*4+2] + gbv;
            float gdB = red[rB*4+0] + red[rB*4+2] + gbv;
            float n2A = red[rA*4+1] + red[rA*4+3];
            float n2B = red[rB*4+1] + red[rB*4+3];
            float gateA = 1.f / (1.f + expf(-gdA));
            float gateB = 1.f / (1.f + expf(-gdB));
            int stableA = (gateA * 0.1f * sqrtf(n2A)) < 0.1f;
            int stableB = (gateB * 0.1f * sqrtf(n2B)) < 0.1f;
            #pragma unroll
            for (int ni = 0; ni < 8; ni++) {
                const int c0 = wn + ni*8 + 2*t4;
                float2 cA = *reinterpret_cast<const float2*>(cur + (size_t)(m0+rA)*128 + c0);
                float2 cB = *reinterpret_cast<const float2*>(cur + (size_t)(m0+rB)*128 + c0);
                float2 bb = *reinterpret_cast<const float2*>(b2 + c0);
                float syA0 = acc[mi][ni][0] + bb.x, syA1 = acc[mi][ni][1] + bb.y;
                float syB0 = acc[mi][ni][2] + bb.x, syB1 = acc[mi][ni][3] + bb.y;
                float2 o0, o1;
                o0.x = cA.x; o0.y = cA.y; o1.x = cB.x; o1.y = cB.y;
                if (flg) {
                    o0.x += gateA * (syA0 - cA.x*amA) * 0.1f;
                    o0.y += gateA * (syA1 - cA.y*amA) * 0.1f;
                    o1.x += gateB * (syB0 - cB.x*amB) * 0.1f;
                    o1.y += gateB * (syB1 - cB.y*amB) * 0.1f;
                }
                *reinterpret_cast<float2*>(cur + (size_t)(m0+rA)*128 + c0) = o0;
                *reinterpret_cast<float2*>(cur + (size_t)(m0+rB)*128 + c0) = o1;
                *reinterpret_cast<__half2*>(&smh[rA*HSMS + c0]) = __floats2half2_rn(o0.x, o0.y);
                *reinterpret_cast<__half2*>(&smh[rB*HSMS + c0]) = __floats2half2_rn(o1.x, o1.y);
            }
            if ((warp & 1) == 0 && t4 == 0) {
                int actA = amA > 0.f, actB = amB > 0.f;
                int naA = actA && !stableA;
                int naB = actB && !stableB;
                if (flg) { s_act[rA] = naA; s_act[rB] = naB; }
                int effA = flg ? naA : actA;
                int effB = flg ? naB : actB;
                if (effA | effB) s_any = 1;
            }
        }
        __syncthreads();

        if (r + 1 < NROUNDS) {
            if (tid == 0) {
                if (s_any) atomicOr(&anyf[r], 1);
                __threadfence();
                atomicAdd(&cnt[r], 1);
                while (atomicAdd(&cnt[r], 0) < (int)gridDim.x) {}
                s_flag = (atomicOr(&anyf[r], 0) != 0) ? 1 : 0;
                s_any = 0;
            }
            __syncthreads();
        }
    }
}

// ---------------- single prep kernel (fp16 weight copies) ---------------------
__global__ void prep_all(
    const float* __restrict__ wq, const float* __restrict__ wk,
    const float* __restrict__ wv, const float* __restrict__ tw,
    const float* __restrict__ w2, const float* __restrict__ w1,
    const float* __restrict__ tb, const float* __restrict__ ab,
    __half* __restrict__ wqkvr, __half* __restrict__ twr,
    __half* __restrict__ w2r, __half* __restrict__ wdr,
    __half* __restrict__ w1cr, float* __restrict__ cvec,
    int* __restrict__ cnt, int* __restrict__ anyf)
{
    int idx = blockIdx.x * blockDim.x + threadIdx.x;
    const int WN4 = DHEAD*DMODEL/4;
    const int T4  = DHEAD*DHEAD/4;
    if (idx < 3*WN4) {
        const float* src = (idx < WN4) ? wq : (idx < 2*WN4 ? wk : wv);
        int off = (idx < WN4) ? idx : (idx < 2*WN4 ? idx - WN4 : idx - 2*WN4);
        float4 vv = reinterpret_cast<const float4*>(src)[off];
        reinterpret_cast<__half2*>(wqkvr)[2*idx]   = __floats2half2_rn(vv.x, vv.y);
        reinterpret_cast<__half2*>(wqkvr)[2*idx+1] = __floats2half2_rn(vv.z, vv.w);
        return;
    }
    idx -= 3*WN4;
    if (idx < T4) {
        float4 vv = reinterpret_cast<const float4*>(tw)[idx];
        reinterpret_cast<__half2*>(twr)[2*idx]   = __floats2half2_rn(vv.x, vv.y);
        reinterpret_cast<__half2*>(twr)[2*idx+1] = __floats2half2_rn(vv.z, vv.w);
        return;
    }
    idx -= T4;
    if (idx < T4) {
        float4 vv = reinterpret_cast<const float4*>(w2)[idx];
        reinterpret_cast<__half2*>(w2r)[2*idx]   = __floats2half2_rn(vv.x, vv.y);
        reinterpret_cast<__half2*>(w2r)[2*idx+1] = __floats2half2_rn(vv.z, vv.w);
        return;
    }
    idx -= T4;
    if (idx < DHEAD*DHEAD) {
        int j = idx >> 7, i = idx & 127;
        wdr[idx]  = __float2half_rn(w1[j*384 + i] - w1[j*384 + 128 + i]);
        w1cr[idx] = __float2half_rn(w1[j*384 + 256 + i]);
        return;
    }
    idx -= DHEAD*DHEAD;
    if (idx < DHEAD) {
        float s = 0.f;
        for (int i = 0; i < 128; i++)
            s += tb[i]*w1[idx*384 + i] + ab[i]*w1[idx*384 + 128 + i];
        cvec[idx] = s;
        return;
    }
    idx -= DHEAD;
    if (idx < NROUNDS) { cnt[idx] = 0; return; }
    idx -= NROUNDS;
    if (idx < NROUNDS) { anyf[idx] = 0; return; }
}
#define PREP_ITEMS (3*(DHEAD*DMODEL/4) + 2*(DHEAD*DHEAD/4) + DHEAD*DHEAD + DHEAD + 2*NROUNDS)

// ---------------- launch ------------------------------------------------------
extern "C" void kernel_launch(void* const* d_in, const int* in_sizes, int n_in,
                              void* d_out, int out_size)
{
    (void)in_sizes; (void)n_in; (void)out_size;
    const float* x  = (const float*)d_in[0];
    const float* wq = (const float*)d_in[1];
    const float* wk = (const float*)d_in[2];
    const float* wv = (const float*)d_in[3];
    const float* tw = (const float*)d_in[4];
    const float* tb = (const float*)d_in[5];
    const float* ab = (const float*)d_in[6];
    const float* w1 = (const float*)d_in[7];
    const float* b1 = (const float*)d_in[8];
    const float* w2 = (const float*)d_in[9];
    const float* b2 = (const float*)d_in[10];
    const float* gw = (const float*)d_in[11];
    const float* gb = (const float*)d_in[12];
    float* cur = (float*)d_out;

    __half *qkv,*curR,*wqkvr,*twr,*w2r,*wdr,*w1cr;
    float *cvec;
    int *cnt,*anyf;
    cudaGetSymbolAddress((void**)&qkv,    g_qkv);
    cudaGetSymbolAddress((void**)&curR,   g_curR);
    cudaGetSymbolAddress((void**)&wqkvr,  g_wqkvr);
    cudaGetSymbolAddress((void**)&twr,    g_twr);
    cudaGetSymbolAddress((void**)&w2r,    g_w2r);
    cudaGetSymbolAddress((void**)&wdr,    g_wdr);
    cudaGetSymbolAddress((void**)&w1cr,   g_w1cr);
    cudaGetSymbolAddress((void**)&cvec,   g_cvec);
    cudaGetSymbolAddress((void**)&cnt,    g_cnt);
    cudaGetSymbolAddress((void**)&anyf,   g_any);

    cudaFuncSetAttribute(qkv_gemm,   cudaFuncAttributeMaxDynamicSharedMemorySize, QKV_SMEM_BYTES);
    cudaFuncSetAttribute(flash_attn, cudaFuncAttributeMaxDynamicSharedMemorySize, FL_SMEM_BYTES);
    cudaFuncSetAttribute(rounds_all, cudaFuncAttributeMaxDynamicSharedMemorySize, RALL_SMEM_BYTES);

    prep_all<<<(PREP_ITEMS + 255)/256, 256>>>(
        wq, wk, wv, tw, w2, w1, tb, ab,
        wqkvr, twr, w2r, wdr, w1cr, cvec, cnt, anyf);

    qkv_gemm<<<dim3(3, MTOK/128), 256, QKV_SMEM_BYTES>>>(x, wqkvr, qkv);

    flash_attn<<<dim3(SEQ/128, BATCH), 256, FL_SMEM_BYTES>>>(
        qkv, qkv + (size_t)MTOK*DHEAD, qkv + 2*(size_t)MTOK*DHEAD, cur, curR);

    rounds_all<<<MTOK/128, 256, RALL_SMEM_BYTES>>>(
        cur, curR, twr, wdr, w1cr, w2r, cvec, b1, b2, gw, gb, cnt, anyf);
}

// round 16
// speedup vs baseline: 1.0539x; 1.0112x over previous
#include <cuda_runtime.h>
#include <cuda_fp16.h>
#include <math.h>
#include <stdint.h>

#define BATCH   8
#define SEQ     2048
#define DMODEL  1024
#define DHEAD   128
#define MTOK    (BATCH*SEQ)          // 16384
#define NROUNDS 3
#define SCALE_F 0.08838834764831843f // 1/sqrt(128)
#define LOG2E_F 1.4426950408889634f
#define SLG_F   (SCALE_F*LOG2E_F)
#define POFF_F  6.0f                 // constant exponent offset (cancels via l)

// ---------------- device scratch (no runtime allocation allowed) -------------
__device__ __align__(256) __half g_qkv[3*MTOK*DHEAD];         // q,k,v fp16
__device__ __align__(256) __half g_curR[MTOK*DHEAD];          // fp16 copy of cur
__device__ __align__(256) __half g_wqkvr[3*DHEAD*DMODEL];
__device__ __align__(256) __half g_twr[DHEAD*DHEAD];
__device__ __align__(256) __half g_w2r[DHEAD*DHEAD];
__device__ __align__(256) __half g_wdr[DHEAD*DHEAD];
__device__ __align__(256) __half g_w1cr[DHEAD*DHEAD];
__device__ float g_cvec[DHEAD];
__device__ int   g_cnt[NROUNDS];
__device__ int   g_any[NROUNDS];

// ---------------- PTX helpers -------------------------------------------------
__device__ __forceinline__ uint32_t s2u(const void* p) {
    uint32_t a;
    asm("{ .reg .u64 t; cvta.to.shared.u64 t, %1; cvt.u32.u64 %0, t; }" : "=r"(a) : "l"(p));
    return a;
}
__device__ __forceinline__ void cp_async16(uint32_t dst, const void* src) {
    asm volatile("cp.async.cg.shared.global [%0], [%1], 16;" :: "r"(dst), "l"(src) : "memory");
}
#define CP_COMMIT() asm volatile("cp.async.commit_group;" ::: "memory")
#define CP_WAIT(N)  asm volatile("cp.async.wait_group %0;" :: "n"(N) : "memory")
#define U32(p) (*reinterpret_cast<const uint32_t*>(p))

__device__ __forceinline__ uint32_t pk(float lo, float hi) {
    __half2 h = __floats2half2_rn(lo, hi);
    return *reinterpret_cast<uint32_t*>(&h);
}
__device__ __forceinline__ float ex2f(float x) {
    float y;
    asm("ex2.approx.ftz.f32 %0, %1;" : "=f"(y) : "f"(x));
    return y;
}
__device__ __forceinline__ float sigmoidf_fast(float x) {
    return 1.f / (1.f + ex2f(-x * LOG2E_F));
}

__device__ __forceinline__ void mma_f16(
    float& c0, float& c1, float& c2, float& c3,
    uint32_t a0, uint32_t a1, uint32_t a2, uint32_t a3,
    uint32_t b0, uint32_t b1)
{
    asm volatile(
        "mma.sync.aligned.m16n8k16.row.col.f32.f16.f16.f32 "
        "{%0,%1,%2,%3}, {%4,%5,%6,%7}, {%8,%9}, {%0,%1,%2,%3};"
        : "+f"(c0), "+f"(c1), "+f"(c2), "+f"(c3)
        : "r"(a0), "r"(a1), "r"(a2), "r"(a3), "r"(b0), "r"(b1));
}

__device__ __forceinline__ void ldsm4(uint32_t& d0, uint32_t& d1, uint32_t& d2,
                                      uint32_t& d3, uint32_t addr)
{
    asm volatile("ldmatrix.sync.aligned.m8n8.x4.shared.b16 {%0,%1,%2,%3}, [%4];"
        : "=r"(d0), "=r"(d1), "=r"(d2), "=r"(d3) : "r"(addr));
}
__device__ __forceinline__ void ldsm4t(uint32_t& d0, uint32_t& d1, uint32_t& d2,
                                       uint32_t& d3, uint32_t addr)
{
    asm volatile("ldmatrix.sync.aligned.m8n8.x4.trans.shared.b16 {%0,%1,%2,%3}, [%4];"
        : "=r"(d0), "=r"(d1), "=r"(d2), "=r"(d3) : "r"(addr));
}

// ---------------- QKV GEMM (fp16 mma, fp32 x converted in-kernel) -------------
#define QSA 40
#define QTILE_H (128*QSA)
#define QSTG_H (2*QTILE_H)
#define QKV_SMEM_BYTES (2*QSTG_H*2)   // 40960

__global__ __launch_bounds__(256) void qkv_gemm(
    const float* __restrict__ X, const __half* __restrict__ W,
    __half* __restrict__ out)
{
    extern __shared__ char smraw[];
    __half* smh = (__half*)smraw;
    const uint32_t sm_u = s2u(smh);
    const int z = blockIdx.x;
    const __half* B = W + (size_t)z*DHEAD*DMODEL;
    __half* C = out + (size_t)z*MTOK*DHEAD;
    const int tid = threadIdx.x, lane = tid & 31, warp = tid >> 5;
    const int wm = (warp >> 1) * 32, wn = (warp & 1) * 64;
    const int m0 = blockIdx.y * 128;
    const int lrow = tid >> 3, lc4 = (tid & 7) * 4;
    const int brow = tid >> 2, bc8 = (tid & 3) * 8;
    const int g = lane >> 2, t4 = lane & 3;
    const int nK = DMODEL >> 5;   // 32

    float4 areg[4];
    {
        const float* Ag = X + (size_t)m0*DMODEL + lc4;
        #pragma unroll
        for (int it = 0; it < 4; it++)
            areg[it] = *reinterpret_cast<const float4*>(Ag + (size_t)(lrow+it*32)*DMODEL);
        #pragma unroll
        for (int itb = 0; itb < 2; itb++)
            cp_async16(sm_u + (uint32_t)(QTILE_H + (brow+itb*64)*QSA + bc8)*2u,
                       B + (size_t)(brow+itb*64)*DMODEL + bc8);
        CP_COMMIT();
        #pragma unroll
        for (int it = 0; it < 4; it++) {
            float4 v = areg[it];
            uint2 h2 = make_uint2(pk(v.x, v.y), pk(v.z, v.w));
            *reinterpret_cast<uint2*>(&smh[(lrow+it*32)*QSA + lc4]) = h2;
        }
    }

    float acc[2][8][4];
    #pragma unroll
    for (int mi = 0; mi < 2; mi++)
        #pragma unroll
        for (int ni = 0; ni < 8; ni++)
            #pragma unroll
            for (int j = 0; j < 4; j++) acc[mi][ni][j] = 0.f;

    for (int kt = 0; kt < nK; kt++) {
        const int cs = kt & 1;
        if (kt + 1 < nK) {
            const int ko = (kt+1)*32;
            const float* Ag = X + (size_t)m0*DMODEL + ko + lc4;
            #pragma unroll
            for (int it = 0; it < 4; it++)
                areg[it] = *reinterpret_cast<const float4*>(Ag + (size_t)(lrow+it*32)*DMODEL);
            const int ns = cs ^ 1;
            #pragma unroll
            for (int itb = 0; itb < 2; itb++)
                cp_async16(sm_u + (uint32_t)(ns*QSTG_H + QTILE_H + (brow+itb*64)*QSA + bc8)*2u,
                           B + (size_t)(brow+itb*64)*DMODEL + ko + bc8);
            CP_COMMIT();
            CP_WAIT(1);
        } else {
            CP_WAIT(0);
        }
        __syncthreads();

        const __half* Ash = smh + cs*QSTG_H;
        const __half* Bsh = Ash + QTILE_H;
        #pragma unroll
        for (int kk = 0; kk < 2; kk++) {
            const int k0 = kk*16 + 2*t4;
            uint32_t a[2][4];
            #pragma unroll
            for (int mi = 0; mi < 2; mi++) {
                const __half* ap = Ash + (wm + mi*16 + g)*QSA + k0;
                a[mi][0] = U32(ap);
                a[mi][1] = U32(ap + 8*QSA);
                a[mi][2] = U32(ap + 8);
                a[mi][3] = U32(ap + 8*QSA + 8);
            }
            #pragma unroll
            for (int ni = 0; ni < 8; ni++) {
                const __half* bp = Bsh + (wn + ni*8 + g)*QSA + k0;
                uint32_t b0 = U32(bp), b1 = U32(bp + 8);
                #pragma unroll
                for (int mi = 0; mi < 2; mi++)
                    mma_f16(acc[mi][ni][0], acc[mi][ni][1], acc[mi][ni][2], acc[mi][ni][3],
                            a[mi][0], a[mi][1], a[mi][2], a[mi][3], b0, b1);
            }
        }
        if (kt + 1 < nK) {
            const int ns = cs ^ 1;
            __half* Ad = smh + ns*QSTG_H;
            #pragma unroll
            for (int it = 0; it < 4; it++) {
                float4 v = areg[it];
                uint2 h2 = make_uint2(pk(v.x, v.y), pk(v.z, v.w));
                *reinterpret_cast<uint2*>(&Ad[(lrow+it*32)*QSA + lc4]) = h2;
            }
        }
        __syncthreads();
    }

    // epilogue: pair adjacent ni (8-col blocks) into single 8B stores
    #pragma unroll
    for (int mi = 0; mi < 2; mi++) {
        const int rA = m0 + wm + mi*16 + g, rB = rA + 8;
        #pragma unroll
        for (int nj = 0; nj < 4; nj++) {
            const int c0 = wn + nj*16 + 2*t4;
            uint2 sA, sB;
            sA.x = pk(acc[mi][2*nj][0],   acc[mi][2*nj][1]);
            sB.x = pk(acc[mi][2*nj][2],   acc[mi][2*nj][3]);
            sA.y = pk(acc[mi][2*nj+1][0], acc[mi][2*nj+1][1]);
            sB.y = pk(acc[mi][2*nj+1][2], acc[mi][2*nj+1][3]);
            // note: the two half2 are 8 columns apart -> cannot fuse into one
            // contiguous store; keep as two 4B stores at c0 and c0+8.
            *reinterpret_cast<uint32_t*>(C + (size_t)rA*DHEAD + c0)     = sA.x;
            *reinterpret_cast<uint32_t*>(C + (size_t)rA*DHEAD + c0 + 8) = sA.y;
            *reinterpret_cast<uint32_t*>(C + (size_t)rB*DHEAD + c0)     = sB.x;
            *reinterpret_cast<uint32_t*>(C + (size_t)rB*DHEAD + c0 + 8) = sB.y;
        }
    }
}

// ---------------- flash attention (exact R12 best-known shape) ----------------
#define SKV 136
#define FH_K 0
#define FH_V (2*64*SKV)
#define FL_SMEM_BYTES ((FH_V + 2*64*SKV)*2)   // 69632

__global__ __launch_bounds__(256) void flash_attn(
    const __half* __restrict__ q, const __half* __restrict__ k,
    const __half* __restrict__ v, float* __restrict__ outc,
    __half* __restrict__ outR)
{
    extern __shared__ char smraw[];
    __half* smh = (__half*)smraw;
    const uint32_t sm_u = s2u(smh);
    const int b   = blockIdx.y;
    const int qb  = blockIdx.x * 128;
    const int tid = threadIdx.x, lane = tid & 31, warp = tid >> 5;
    const int g   = lane >> 2, t4 = lane & 3;

    const __half* qB = q + ((size_t)b*SEQ + qb)*DHEAD;
    const __half* kB = k + (size_t)b*SEQ*DHEAD;
    const __half* vB = v + (size_t)b*SEQ*DHEAD;

    const int kc = tid >> 4;
    const int kf = (tid & 15) * 8;

    const int krow = (lane >> 4)*8 + (lane & 7);
    const int kcol = ((lane >> 3) & 1) * 8;

    uint32_t qa[8][4];
    {
        const __half* q0 = qB + (size_t)(warp*16 + g)*DHEAD;
        const __half* q8 = q0 + 8*DHEAD;
        #pragma unroll
        for (int ks = 0; ks < 8; ks++) {
            const int o = ks*16 + 2*t4;
            qa[ks][0] = U32(q0 + o);
            qa[ks][1] = U32(q8 + o);
            qa[ks][2] = U32(q0 + o + 8);
            qa[ks][3] = U32(q8 + o + 8);
        }
    }

    float oacc[16][4];
    #pragma unroll
    for (int ni = 0; ni < 16; ni++)
        #pragma unroll
        for (int j = 0; j < 4; j++) oacc[ni][j] = 0.f;
    float l0 = 0.f, l1 = 0.f;

    {
        #pragma unroll
        for (int it = 0; it < 4; it++) {
            cp_async16(sm_u + (uint32_t)(FH_K + (kc + it*16)*SKV + kf)*2u,
                       kB + (size_t)(kc + it*16)*DHEAD + kf);
            cp_async16(sm_u + (uint32_t)(FH_V + (kc + it*16)*SKV + kf)*2u,
                       vB + (size_t)(kc + it*16)*DHEAD + kf);
        }
        CP_COMMIT();
    }

    const int nTiles = SEQ / 64;  // 32
    for (int t = 0; t < nTiles; t++) {
        const int cs = t & 1;
        if (t + 1 < nTiles) {
            const int ns = cs ^ 1;
            const int kv1 = (t+1) * 64;
            #pragma unroll
            for (int it = 0; it < 4; it++) {
                cp_async16(sm_u + (uint32_t)(FH_K + ns*64*SKV + (kc + it*16)*SKV + kf)*2u,
                           kB + (size_t)(kv1 + kc + it*16)*DHEAD + kf);
                cp_async16(sm_u + (uint32_t)(FH_V + ns*64*SKV + (kc + it*16)*SKV + kf)*2u,
                           vB + (size_t)(kv1 + kc + it*16)*DHEAD + kf);
            }
            CP_COMMIT();
            CP_WAIT(1);
        } else {
            CP_WAIT(0);
        }
        __syncthreads();

        const uint32_t kb0 = sm_u + (uint32_t)(FH_K + cs*64*SKV + krow*SKV + kcol)*2u;
        const uint32_t vb0 = sm_u + (uint32_t)(FH_V + cs*64*SKV + lane*SKV)*2u;

        float sacc[8][4];
        #pragma unroll
        for (int ni = 0; ni < 8; ni++)
            #pragma unroll
            for (int j = 0; j < 4; j++) sacc[ni][j] = 0.f;
        #pragma unroll
        for (int ks = 0; ks < 8; ks++) {
            #pragma unroll
            for (int nj = 0; nj < 4; nj++) {
                uint32_t b0, b1, b2, b3;
                ldsm4(b0, b1, b2, b3, kb0 + (uint32_t)(nj*16*SKV + ks*16)*2u);
                mma_f16(sacc[2*nj][0], sacc[2*nj][1], sacc[2*nj][2], sacc[2*nj][3],
                        qa[ks][0], qa[ks][1], qa[ks][2], qa[ks][3], b0, b1);
                mma_f16(sacc[2*nj+1][0], sacc[2*nj+1][1], sacc[2*nj+1][2], sacc[2*nj+1][3],
                        qa[ks][0], qa[ks][1], qa[ks][2], qa[ks][3], b2, b3);
            }
        }

        // fixed-base softmax: P = exp2(s*scale*log2e - C); C cancels via l
        float rs0 = 0.f, rs1 = 0.f;
        uint32_t pa[4][4];
        #pragma unroll
        for (int j = 0; j < 4; j++) {
            const int n0i = 2*j, n1i = 2*j + 1;
            float p00 = ex2f(fmaf(sacc[n0i][0], SLG_F, -POFF_F));
            float p01 = ex2f(fmaf(sacc[n0i][1], SLG_F, -POFF_F));
            float p02 = ex2f(fmaf(sacc[n0i][2], SLG_F, -POFF_F));
            float p03 = ex2f(fmaf(sacc[n0i][3], SLG_F, -POFF_F));
            float p10 = ex2f(fmaf(sacc[n1i][0], SLG_F, -POFF_F));
            float p11 = ex2f(fmaf(sacc[n1i][1], SLG_F, -POFF_F));
            float p12 = ex2f(fmaf(sacc[n1i][2], SLG_F, -POFF_F));
            float p13 = ex2f(fmaf(sacc[n1i][3], SLG_F, -POFF_F));
            rs0 += p00 + p01 + p10 + p11;
            rs1 += p02 + p03 + p12 + p13;
            pa[j][0] = pk(p00, p01);
            pa[j][1] = pk(p02, p03);
            pa[j][2] = pk(p10, p11);
            pa[j][3] = pk(p12, p13);
        }
        rs0 += __shfl_xor_sync(0xffffffffu, rs0, 1);
        rs0 += __shfl_xor_sync(0xffffffffu, rs0, 2);
        rs1 += __shfl_xor_sync(0xffffffffu, rs1, 1);
        rs1 += __shfl_xor_sync(0xffffffffu, rs1, 2);
        l0 += rs0;
        l1 += rs1;

        #pragma unroll
        for (int jp = 0; jp < 2; jp++) {
            const uint32_t ab = vb0 + (uint32_t)(jp*32*SKV)*2u;
            #pragma unroll
            for (int ni = 0; ni < 16; ni++) {
                uint32_t b0, b1, b2, b3;
                ldsm4t(b0, b1, b2, b3, ab + ni*16);
                mma_f16(oacc[ni][0], oacc[ni][1], oacc[ni][2], oacc[ni][3],
                        pa[2*jp][0], pa[2*jp][1], pa[2*jp][2], pa[2*jp][3], b0, b1);
                mma_f16(oacc[ni][0], oacc[ni][1], oacc[ni][2], oacc[ni][3],
                        pa[2*jp+1][0], pa[2*jp+1][1], pa[2*jp+1][2], pa[2*jp+1][3], b2, b3);
            }
        }
        __syncthreads();
    }

    const float inv0 = 1.f / l0, inv1 = 1.f / l1;
    const size_t rowA = (size_t)b*SEQ + qb + warp*16 + g;
    const size_t rowB = rowA + 8;
    #pragma unroll
    for (int ni = 0; ni < 16; ni++) {
        const int c0 = ni*8 + 2*t4;
        float2 v0, v1;
        v0.x = oacc[ni][0]*inv0; v0.y = oacc[ni][1]*inv0;
        v1.x = oacc[ni][2]*inv1; v1.y = oacc[ni][3]*inv1;
        *reinterpret_cast<float2*>(outc + rowA*DHEAD + c0) = v0;
        *reinterpret_cast<float2*>(outc + rowB*DHEAD + c0) = v1;
        *reinterpret_cast<__half2*>(outR + rowA*DHEAD + c0) = __floats2half2_rn(v0.x, v0.y);
        *reinterpret_cast<__half2*>(outR + rowB*DHEAD + c0) = __floats2half2_rn(v1.x, v1.y);
    }
}

// ---------------- persistent merged rounds kernel (fp16, 256 thr, ldmatrix) ---
#define HSMS 136
#define RB_T0   0
#define RB_T1   34816
#define RB_T2   69632
#define RB_T3   104448
#define RB_T4   139264
#define RB_RED  174080
#define RB_ACT  176128
#define RALL_SMEM_BYTES (RB_ACT + 128*4)   // 176640
#define ZFS 132

__device__ __forceinline__ void load_tile128h(uint32_t sdst_bytes,
                                              const __half* __restrict__ src, int tid)
{
    const int row = tid >> 4, c8 = (tid & 15) * 8;
    #pragma unroll
    for (int it = 0; it < 8; it++)
        cp_async16(sdst_bytes + (uint32_t)((row + it*16)*HSMS + c8)*2u,
                   src + (size_t)(row + it*16)*128 + c8);
}

__device__ __forceinline__ void mma_128x128h(uint32_t aAddr, uint32_t bAddr,
                                             float acc[2][8][4])
{
    #pragma unroll
    for (int ks = 0; ks < 8; ks++) {
        uint32_t a[2][4];
        #pragma unroll
        for (int mi = 0; mi < 2; mi++)
            ldsm4(a[mi][0], a[mi][1], a[mi][2], a[mi][3],
                  aAddr + (uint32_t)(mi*16*HSMS + ks*16)*2u);
        #pragma unroll
        for (int nj = 0; nj < 4; nj++) {
            uint32_t b0, b1, b2, b3;
            ldsm4(b0, b1, b2, b3, bAddr + (uint32_t)(nj*16*HSMS + ks*16)*2u);
            #pragma unroll
            for (int mi = 0; mi < 2; mi++) {
                mma_f16(acc[mi][2*nj][0], acc[mi][2*nj][1], acc[mi][2*nj][2], acc[mi][2*nj][3],
                        a[mi][0], a[mi][1], a[mi][2], a[mi][3], b0, b1);
                mma_f16(acc[mi][2*nj+1][0], acc[mi][2*nj+1][1], acc[mi][2*nj+1][2], acc[mi][2*nj+1][3],
                        a[mi][0], a[mi][1], a[mi][2], a[mi][3], b2, b3);
            }
        }
    }
}

#define ZERO_ACC(acc) { \
    _Pragma("unroll") for (int mi = 0; mi < 2; mi++) \
        _Pragma("unroll") for (int ni = 0; ni < 8; ni++) \
            _Pragma("unroll") for (int j = 0; j < 4; j++) acc[mi][ni][j] = 0.f; }

__global__ __launch_bounds__(256) void rounds_all(
    float* __restrict__ cur, const __half* __restrict__ curR,
    const __half* __restrict__ tw, const __half* __restrict__ wd,
    const __half* __restrict__ w1c, const __half* __restrict__ w2,
    const float* __restrict__ cvec, const float* __restrict__ b1,
    const float* __restrict__ b2, const float* __restrict__ gw,
    const float* __restrict__ gb,
    int* __restrict__ cnt, int* __restrict__ anyf)
{
    extern __shared__ char smraw[];
    __half* smh = (__half*)smraw;
    const uint32_t sm_u = s2u(smraw);
    float* ZF  = reinterpret_cast<float*>(smraw + RB_T1);
    float* red = reinterpret_cast<float*>(smraw + RB_RED);
    int* s_act = reinterpret_cast<int*>(smraw + RB_ACT);
    __shared__ int s_flag, s_any;
    const int tid = threadIdx.x, lane = tid & 31, warp = tid >> 5;
    const int wm = (warp >> 1) * 32, wn = (warp & 1) * 64;
    const int g = lane >> 2, t4 = lane & 3;
    const int m0 = blockIdx.x * 128;

    const uint32_t aOff = (uint32_t)(((wm + (lane & 7) + 8*((lane >> 3) & 1))*HSMS
                                      + (lane >> 4)*8) * 2);
    const uint32_t bOff = (uint32_t)(((wn + (lane >> 4)*8 + (lane & 7))*HSMS
                                      + ((lane >> 3) & 1)*8) * 2);

    load_tile128h(sm_u + RB_T0, curR + (size_t)m0*128, tid);
    load_tile128h(sm_u + RB_T1, tw, tid);
    load_tile128h(sm_u + RB_T2, wd, tid);
    load_tile128h(sm_u + RB_T3, w1c, tid);
    load_tile128h(sm_u + RB_T4, w2, tid);
    CP_COMMIT(); CP_WAIT(0);
    if (tid < 128) s_act[tid] = 1;
    if (tid == 0) { s_flag = 1; s_any = 0; }
    __syncthreads();

    float acc[2][8][4];

    ZERO_ACC(acc);
    mma_128x128h(sm_u + RB_T0 + aOff, sm_u + RB_T1 + bOff, acc);
    __syncthreads();
    {
        __half* Ps = smh + RB_T1/2;
        #pragma unroll
        for (int mi = 0; mi < 2; mi++) {
            const int rA = wm + mi*16 + g, rB = rA + 8;
            #pragma unroll
            for (int ni = 0; ni < 8; ni++) {
                const int c0 = wn + ni*8 + 2*t4;
                *reinterpret_cast<__half2*>(&Ps[rA*HSMS + c0]) =
                    __floats2half2_rn(acc[mi][ni][0], acc[mi][ni][1]);
                *reinterpret_cast<__half2*>(&Ps[rB*HSMS + c0]) =
                    __floats2half2_rn(acc[mi][ni][2], acc[mi][ni][3]);
            }
        }
    }
    __syncthreads();
    ZERO_ACC(acc);
    mma_128x128h(sm_u + RB_T1 + aOff, sm_u + RB_T2 + bOff, acc);
    __syncthreads();
    {
        #pragma unroll
        for (int mi = 0; mi < 2; mi++) {
            const int rA = wm + mi*16 + g, rB = rA + 8;
            #pragma unroll
            for (int ni = 0; ni < 8; ni++) {
                const int c0 = wn + ni*8 + 2*t4;
                float2 v0, v1;
                v0.x = acc[mi][ni][0]; v0.y = acc[mi][ni][1];
                v1.x = acc[mi][ni][2]; v1.y = acc[mi][ni][3];
                *reinterpret_cast<float2*>(&ZF[rA*ZFS + c0]) = v0;
                *reinterpret_cast<float2*>(&ZF[rB*ZFS + c0]) = v1;
            }
        }
    }
    __syncthreads();

    for (int r = 0; r < NROUNDS; r++) {
        ZERO_ACC(acc);
        mma_128x128h(sm_u + RB_T0 + aOff, sm_u + RB_T3 + bOff, acc);
        __syncthreads();

        float amr[4];
        #pragma unroll
        for (int mi = 0; mi < 2; mi++) {
            const int rA = wm + mi*16 + g, rB = rA + 8;
            const float amA = s_act[rA] ? 1.f : 0.f;
            const float amB = s_act[rB] ? 1.f : 0.f;
            amr[mi*2] = amA; amr[mi*2+1] = amB;
            #pragma unroll
            for (int ni = 0; ni < 8; ni++) {
                const int c0 = wn + ni*8 + 2*t4;
                float2 zA = *reinterpret_cast<const float2*>(&ZF[rA*ZFS + c0]);
                float2 zB = *reinterpret_cast<const float2*>(&ZF[rB*ZFS + c0]);
                float2 cc = *reinterpret_cast<const float2*>(cvec + c0);
                float2 bb = *reinterpret_cast<const float2*>(b1 + c0);
                float h00 = fmaxf(fmaf(amA, acc[mi][ni][0] + zA.x + cc.x, bb.x), 0.f);
                float h01 = fmaxf(fmaf(amA, acc[mi][ni][1] + zA.y + cc.y, bb.y), 0.f);
                float h10 = fmaxf(fmaf(amB, acc[mi][ni][2] + zB.x + cc.x, bb.x), 0.f);
                float h11 = fmaxf(fmaf(amB, acc[mi][ni][3] + zB.y + cc.y, bb.y), 0.f);
                *reinterpret_cast<__half2*>(&smh[rA*HSMS + c0]) = __floats2half2_rn(h00, h01);
                *reinterpret_cast<__half2*>(&smh[rB*HSMS + c0]) = __floats2half2_rn(h10, h11);
            }
        }
        __syncthreads();

        ZERO_ACC(acc);
        mma_128x128h(sm_u + RB_T0 + aOff, sm_u + RB_T4 + bOff, acc);

        const int flg = s_flag;
        float d1[4] = {0,0,0,0}, nn[4] = {0,0,0,0};
        #pragma unroll
        for (int mi = 0; mi < 2; mi++) {
            const int rA = wm + mi*16 + g, rB = rA + 8;
            const float amA = amr[mi*2], amB = amr[mi*2+1];
            #pragma unroll
            for (int ni = 0; ni < 8; ni++) {
                const int c0 = wn + ni*8 + 2*t4;
                float2 cA = *reinterpret_cast<const float2*>(cur + (size_t)(m0+rA)*128 + c0);
                float2 cB = *reinterpret_cast<const float2*>(cur + (size_t)(m0+rB)*128 + c0);
                float2 bb = *reinterpret_cast<const float2*>(b2 + c0);
                float2 g1 = *reinterpret_cast<const float2*>(gw + c0);
                float2 g2 = *reinterpret_cast<const float2*>(gw + 128 + c0);
                float syA0 = acc[mi][ni][0] + bb.x, syA1 = acc[mi][ni][1] + bb.y;
                float syB0 = acc[mi][ni][2] + bb.x, syB1 = acc[mi][ni][3] + bb.y;
                float acA0 = cA.x * amA, acA1 = cA.y * amA;
                float acB0 = cB.x * amB, acB1 = cB.y * amB;
                d1[mi*2]   += acA0*g1.x + syA0*g2.x + acA1*g1.y + syA1*g2.y;
                d1[mi*2+1] += acB0*g1.x + syB0*g2.x + acB1*g1.y + syB1*g2.y;
                float dA0 = syA0-acA0, dA1 = syA1-acA1;
                float dB0 = syB0-acB0, dB1 = syB1-acB1;
                nn[mi*2]   += dA0*dA0 + dA1*dA1;
                nn[mi*2+1] += dB0*dB0 + dB1*dB1;
            }
        }
        #pragma unroll
        for (int j = 0; j < 4; j++) {
            d1[j] += __shfl_xor_sync(0xffffffffu, d1[j], 1);
            d1[j] += __shfl_xor_sync(0xffffffffu, d1[j], 2);
            nn[j] += __shfl_xor_sync(0xffffffffu, nn[j], 1);
            nn[j] += __shfl_xor_sync(0xffffffffu, nn[j], 2);
        }
        if (t4 == 0) {
            const int hf = (warp & 1) * 2;
            #pragma unroll
            for (int mi = 0; mi < 2; mi++) {
                const int rA = wm + mi*16 + g, rB = rA + 8;
                red[rA*4 + hf]     = d1[mi*2];
                red[rA*4 + hf + 1] = nn[mi*2];
                red[rB*4 + hf]     = d1[mi*2+1];
                red[rB*4 + hf + 1] = nn[mi*2+1];
            }
        }
        __syncthreads();

        const float gbv = gb[0];
        #pragma unroll
        for (int mi = 0; mi < 2; mi++) {
            const int rA = wm + mi*16 + g, rB = rA + 8;
            const float amA = amr[mi*2], amB = amr[mi*2+1];
            float gdA = red[rA*4+0] + red[rA*4+2] + gbv;
            float gdB = red[rB*4+0] + red[rB*4+2] + gbv;
            float n2A = red[rA*4+1] + red[rA*4+3];
            float n2B = red[rB*4+1] + red[rB*4+3];
            float gateA = sigmoidf_fast(gdA);
            float gateB = sigmoidf_fast(gdB);
            int stableA = (gateA * 0.1f * sqrtf(n2A)) < 0.1f;
            int stableB = (gateB * 0.1f * sqrtf(n2B)) < 0.1f;
            #pragma unroll
            for (int ni = 0; ni < 8; ni++) {
                const int c0 = wn + ni*8 + 2*t4;
                float2 cA = *reinterpret_cast<const float2*>(cur + (size_t)(m0+rA)*128 + c0);
                float2 cB = *reinterpret_cast<const float2*>(cur + (size_t)(m0+rB)*128 + c0);
                float2 bb = *reinterpret_cast<const float2*>(b2 + c0);
                float syA0 = acc[mi][ni][0] + bb.x, syA1 = acc[mi][ni][1] + bb.y;
                float syB0 = acc[mi][ni][2] + bb.x, syB1 = acc[mi][ni][3] + bb.y;
                float2 o0, o1;
                o0.x = cA.x; o0.y = cA.y; o1.x = cB.x; o1.y = cB.y;
                if (flg) {
                    o0.x += gateA * (syA0 - cA.x*amA) * 0.1f;
                    o0.y += gateA * (syA1 - cA.y*amA) * 0.1f;
                    o1.x += gateB * (syB0 - cB.x*amB) * 0.1f;
                    o1.y += gateB * (syB1 - cB.y*amB) * 0.1f;
                }
                *reinterpret_cast<float2*>(cur + (size_t)(m0+rA)*128 + c0) = o0;
                *reinterpret_cast<float2*>(cur + (size_t)(m0+rB)*128 + c0) = o1;
                *reinterpret_cast<__half2*>(&smh[rA*HSMS + c0]) = __floats2half2_rn(o0.x, o0.y);
                *reinterpret_cast<__half2*>(&smh[rB*HSMS + c0]) = __floats2half2_rn(o1.x, o1.y);
            }
            if ((warp & 1) == 0 && t4 == 0) {
                int actA = amA > 0.f, actB = amB > 0.f;
                int naA = actA && !stableA;
                int naB = actB && !stableB;
                if (flg) { s_act[rA] = naA; s_act[rB] = naB; }
                int effA = flg ? naA : actA;
                int effB = flg ? naB : actB;
                if (effA | effB) s_any = 1;
            }
        }
        __syncthreads();

        if (r + 1 < NROUNDS) {
            if (tid == 0) {
                if (s_any) atomicOr(&anyf[r], 1);
                __threadfence();
                atomicAdd(&cnt[r], 1);
                while (atomicAdd(&cnt[r], 0) < (int)gridDim.x) {}
                s_flag = (atomicOr(&anyf[r], 0) != 0) ? 1 : 0;
                s_any = 0;
            }
            __syncthreads();
        }
    }
}

// ---------------- single prep kernel (fp16 weight copies) ---------------------
__global__ void prep_all(
    const float* __restrict__ wq, const float* __restrict__ wk,
    const float* __restrict__ wv, const float* __restrict__ tw,
    const float* __restrict__ w2, const float* __restrict__ w1,
    const float* __restrict__ tb, const float* __restrict__ ab,
    __half* __restrict__ wqkvr, __half* __restrict__ twr,
    __half* __restrict__ w2r, __half* __restrict__ wdr,
    __half* __restrict__ w1cr, float* __restrict__ cvec,
    int* __restrict__ cnt, int* __restrict__ anyf)
{
    int idx = blockIdx.x * blockDim.x + threadIdx.x;
    const int WN4 = DHEAD*DMODEL/4;
    const int T4  = DHEAD*DHEAD/4;
    if (idx < 3*WN4) {
        const float* src = (idx < WN4) ? wq : (idx < 2*WN4 ? wk : wv);
        int off = (idx < WN4) ? idx : (idx < 2*WN4 ? idx - WN4 : idx - 2*WN4);
        float4 vv = reinterpret_cast<const float4*>(src)[off];
        reinterpret_cast<__half2*>(wqkvr)[2*idx]   = __floats2half2_rn(vv.x, vv.y);
        reinterpret_cast<__half2*>(wqkvr)[2*idx+1] = __floats2half2_rn(vv.z, vv.w);
        return;
    }
    idx -= 3*WN4;
    if (idx < T4) {
        float4 vv = reinterpret_cast<const float4*>(tw)[idx];
        reinterpret_cast<__half2*>(twr)[2*idx]   = __floats2half2_rn(vv.x, vv.y);
        reinterpret_cast<__half2*>(twr)[2*idx+1] = __floats2half2_rn(vv.z, vv.w);
        return;
    }
    idx -= T4;
    if (idx < T4) {
        float4 vv = reinterpret_cast<const float4*>(w2)[idx];
        reinterpret_cast<__half2*>(w2r)[2*idx]   = __floats2half2_rn(vv.x, vv.y);
        reinterpret_cast<__half2*>(w2r)[2*idx+1] = __floats2half2_rn(vv.z, vv.w);
        return;
    }
    idx -= T4;
    if (idx < DHEAD*DHEAD) {
        int j = idx >> 7, i = idx & 127;
        wdr[idx]  = __float2half_rn(w1[j*384 + i] - w1[j*384 + 128 + i]);
        w1cr[idx] = __float2half_rn(w1[j*384 + 256 + i]);
        return;
    }
    idx -= DHEAD*DHEAD;
    if (idx < DHEAD) {
        float s = 0.f;
        for (int i = 0; i < 128; i++)
            s += tb[i]*w1[idx*384 + i] + ab[i]*w1[idx*384 + 128 + i];
        cvec[idx] = s;
        return;
    }
    idx -= DHEAD;
    if (idx < NROUNDS) { cnt[idx] = 0; return; }
    idx -= NROUNDS;
    if (idx < NROUNDS) { anyf[idx] = 0; return; }
}
#define PREP_ITEMS (3*(DHEAD*DMODEL/4) + 2*(DHEAD*DHEAD/4) + DHEAD*DHEAD + DHEAD + 2*NROUNDS)

// ---------------- launch ------------------------------------------------------
extern "C" void kernel_launch(void* const* d_in, const int* in_sizes, int n_in,
                              void* d_out, int out_size)
{
    (void)in_sizes; (void)n_in; (void)out_size;
    const float* x  = (const float*)d_in[0];
    const float* wq = (const float*)d_in[1];
    const float* wk = (const float*)d_in[2];
    const float* wv = (const float*)d_in[3];
    const float* tw = (const float*)d_in[4];
    const float* tb = (const float*)d_in[5];
    const float* ab = (const float*)d_in[6];
    const float* w1 = (const float*)d_in[7];
    const float* b1 = (const float*)d_in[8];
    const float* w2 = (const float*)d_in[9];
    const float* b2 = (const float*)d_in[10];
    const float* gw = (const float*)d_in[11];
    const float* gb = (const float*)d_in[12];
    float* cur = (float*)d_out;

    __half *qkv,*curR,*wqkvr,*twr,*w2r,*wdr,*w1cr;
    float *cvec;
    int *cnt,*anyf;
    cudaGetSymbolAddress((void**)&qkv,    g_qkv);
    cudaGetSymbolAddress((void**)&curR,   g_curR);
    cudaGetSymbolAddress((void**)&wqkvr,  g_wqkvr);
    cudaGetSymbolAddress((void**)&twr,    g_twr);
    cudaGetSymbolAddress((void**)&w2r,    g_w2r);
    cudaGetSymbolAddress((void**)&wdr,    g_wdr);
    cudaGetSymbolAddress((void**)&w1cr,   g_w1cr);
    cudaGetSymbolAddress((void**)&cvec,   g_cvec);
    cudaGetSymbolAddress((void**)&cnt,    g_cnt);
    cudaGetSymbolAddress((void**)&anyf,   g_any);

    cudaFuncSetAttribute(qkv_gemm,   cudaFuncAttributeMaxDynamicSharedMemorySize, QKV_SMEM_BYTES);
    cudaFuncSetAttribute(flash_attn, cudaFuncAttributeMaxDynamicSharedMemorySize, FL_SMEM_BYTES);
    cudaFuncSetAttribute(rounds_all, cudaFuncAttributeMaxDynamicSharedMemorySize, RALL_SMEM_BYTES);

    prep_all<<<(PREP_ITEMS + 255)/256, 256>>>(
        wq, wk, wv, tw, w2, w1, tb, ab,
        wqkvr, twr, w2r, wdr, w1cr, cvec, cnt, anyf);

    qkv_gemm<<<dim3(3, MTOK/128), 256, QKV_SMEM_BYTES>>>(x, wqkvr, qkv);

    flash_attn<<<dim3(SEQ/128, BATCH), 256, FL_SMEM_BYTES>>>(
        qkv, qkv + (size_t)MTOK*DHEAD, qkv + 2*(size_t)MTOK*DHEAD, cur, curR);

    rounds_all<<<MTOK/128, 256, RALL_SMEM_BYTES>>>(
        cur, curR, twr, wdr, w1cr, w2r, cvec, b1, b2, gw, gb, cnt, anyf);
}

// round 17
// speedup vs baseline: 1.0783x; 1.0231x over previous
#include <cuda_runtime.h>
#include <cuda_fp16.h>
#include <math.h>
#include <stdint.h>

#define BATCH   8
#define SEQ     2048
#define DMODEL  1024
#define DHEAD   128
#define MTOK    (BATCH*SEQ)          // 16384
#define NROUNDS 3
#define SCALE_F 0.08838834764831843f // 1/sqrt(128)
#define LOG2E_F 1.4426950408889634f
#define SLG_F   (SCALE_F*LOG2E_F)
#define POFF_F  6.0f                 // constant exponent offset (cancels via l)

// ---------------- device scratch (no runtime allocation allowed) -------------
__device__ __align__(256) __half g_qkv[3*MTOK*DHEAD];         // q,k,v fp16
__device__ __align__(256) __half g_curR[MTOK*DHEAD];          // fp16 copy of cur
__device__ __align__(256) __half g_wqkvr[3*DHEAD*DMODEL];
__device__ __align__(256) __half g_twr[DHEAD*DHEAD];
__device__ __align__(256) __half g_w2r[DHEAD*DHEAD];
__device__ __align__(256) __half g_wdr[DHEAD*DHEAD];
__device__ __align__(256) __half g_w1cr[DHEAD*DHEAD];
__device__ float g_cvec[DHEAD];
__device__ int   g_cnt[NROUNDS];
__device__ int   g_any[NROUNDS];

// ---------------- PTX helpers -------------------------------------------------
__device__ __forceinline__ uint32_t s2u(const void* p) {
    uint32_t a;
    asm("{ .reg .u64 t; cvta.to.shared.u64 t, %1; cvt.u32.u64 %0, t; }" : "=r"(a) : "l"(p));
    return a;
}
__device__ __forceinline__ void cp_async16(uint32_t dst, const void* src) {
    asm volatile("cp.async.cg.shared.global [%0], [%1], 16;" :: "r"(dst), "l"(src) : "memory");
}
#define CP_COMMIT() asm volatile("cp.async.commit_group;" ::: "memory")
#define CP_WAIT(N)  asm volatile("cp.async.wait_group %0;" :: "n"(N) : "memory")
#define U32(p) (*reinterpret_cast<const uint32_t*>(p))

__device__ __forceinline__ uint32_t pk(float lo, float hi) {
    __half2 h = __floats2half2_rn(lo, hi);
    return *reinterpret_cast<uint32_t*>(&h);
}
__device__ __forceinline__ float ex2f(float x) {
    float y;
    asm("ex2.approx.ftz.f32 %0, %1;" : "=f"(y) : "f"(x));
    return y;
}
__device__ __forceinline__ float sigmoidf_fast(float x) {
    return 1.f / (1.f + ex2f(-x * LOG2E_F));
}

__device__ __forceinline__ void mma_f16(
    float& c0, float& c1, float& c2, float& c3,
    uint32_t a0, uint32_t a1, uint32_t a2, uint32_t a3,
    uint32_t b0, uint32_t b1)
{
    asm volatile(
        "mma.sync.aligned.m16n8k16.row.col.f32.f16.f16.f32 "
        "{%0,%1,%2,%3}, {%4,%5,%6,%7}, {%8,%9}, {%0,%1,%2,%3};"
        : "+f"(c0), "+f"(c1), "+f"(c2), "+f"(c3)
        : "r"(a0), "r"(a1), "r"(a2), "r"(a3), "r"(b0), "r"(b1));
}

__device__ __forceinline__ void ldsm4(uint32_t& d0, uint32_t& d1, uint32_t& d2,
                                      uint32_t& d3, uint32_t addr)
{
    asm volatile("ldmatrix.sync.aligned.m8n8.x4.shared.b16 {%0,%1,%2,%3}, [%4];"
        : "=r"(d0), "=r"(d1), "=r"(d2), "=r"(d3) : "r"(addr));
}
__device__ __forceinline__ void ldsm4t(uint32_t& d0, uint32_t& d1, uint32_t& d2,
                                       uint32_t& d3, uint32_t addr)
{
    asm volatile("ldmatrix.sync.aligned.m8n8.x4.trans.shared.b16 {%0,%1,%2,%3}, [%4];"
        : "=r"(d0), "=r"(d1), "=r"(d2), "=r"(d3) : "r"(addr));
}

// ---------------- QKV GEMM (fp16 mma, fp32 x converted in-kernel) -------------
#define QSA 40
#define QTILE_H (128*QSA)
#define QSTG_H (2*QTILE_H)
#define QKV_SMEM_BYTES (2*QSTG_H*2)   // 40960

__global__ __launch_bounds__(256) void qkv_gemm(
    const float* __restrict__ X, const __half* __restrict__ W,
    __half* __restrict__ out)
{
    extern __shared__ char smraw[];
    __half* smh = (__half*)smraw;
    const uint32_t sm_u = s2u(smh);
    const int z = blockIdx.x;
    const __half* B = W + (size_t)z*DHEAD*DMODEL;
    __half* C = out + (size_t)z*MTOK*DHEAD;
    const int tid = threadIdx.x, lane = tid & 31, warp = tid >> 5;
    const int wm = (warp >> 1) * 32, wn = (warp & 1) * 64;
    const int m0 = blockIdx.y * 128;
    const int lrow = tid >> 3, lc4 = (tid & 7) * 4;
    const int brow = tid >> 2, bc8 = (tid & 3) * 8;
    const int g = lane >> 2, t4 = lane & 3;
    const int nK = DMODEL >> 5;   // 32

    float4 areg[4];
    {
        const float* Ag = X + (size_t)m0*DMODEL + lc4;
        #pragma unroll
        for (int it = 0; it < 4; it++)
            areg[it] = *reinterpret_cast<const float4*>(Ag + (size_t)(lrow+it*32)*DMODEL);
        #pragma unroll
        for (int itb = 0; itb < 2; itb++)
            cp_async16(sm_u + (uint32_t)(QTILE_H + (brow+itb*64)*QSA + bc8)*2u,
                       B + (size_t)(brow+itb*64)*DMODEL + bc8);
        CP_COMMIT();
        #pragma unroll
        for (int it = 0; it < 4; it++) {
            float4 v = areg[it];
            uint2 h2 = make_uint2(pk(v.x, v.y), pk(v.z, v.w));
            *reinterpret_cast<uint2*>(&smh[(lrow+it*32)*QSA + lc4]) = h2;
        }
    }

    float acc[2][8][4];
    #pragma unroll
    for (int mi = 0; mi < 2; mi++)
        #pragma unroll
        for (int ni = 0; ni < 8; ni++)
            #pragma unroll
            for (int j = 0; j < 4; j++) acc[mi][ni][j] = 0.f;

    for (int kt = 0; kt < nK; kt++) {
        const int cs = kt & 1;
        if (kt + 1 < nK) {
            const int ko = (kt+1)*32;
            const float* Ag = X + (size_t)m0*DMODEL + ko + lc4;
            #pragma unroll
            for (int it = 0; it < 4; it++)
                areg[it] = *reinterpret_cast<const float4*>(Ag + (size_t)(lrow+it*32)*DMODEL);
            const int ns = cs ^ 1;
            #pragma unroll
            for (int itb = 0; itb < 2; itb++)
                cp_async16(sm_u + (uint32_t)(ns*QSTG_H + QTILE_H + (brow+itb*64)*QSA + bc8)*2u,
                           B + (size_t)(brow+itb*64)*DMODEL + ko + bc8);
            CP_COMMIT();
            CP_WAIT(1);
        } else {
            CP_WAIT(0);
        }
        __syncthreads();

        const __half* Ash = smh + cs*QSTG_H;
        const __half* Bsh = Ash + QTILE_H;
        #pragma unroll
        for (int kk = 0; kk < 2; kk++) {
            const int k0 = kk*16 + 2*t4;
            uint32_t a[2][4];
            #pragma unroll
            for (int mi = 0; mi < 2; mi++) {
                const __half* ap = Ash + (wm + mi*16 + g)*QSA + k0;
                a[mi][0] = U32(ap);
                a[mi][1] = U32(ap + 8*QSA);
                a[mi][2] = U32(ap + 8);
                a[mi][3] = U32(ap + 8*QSA + 8);
            }
            #pragma unroll
            for (int ni = 0; ni < 8; ni++) {
                const __half* bp = Bsh + (wn + ni*8 + g)*QSA + k0;
                uint32_t b0 = U32(bp), b1 = U32(bp + 8);
                #pragma unroll
                for (int mi = 0; mi < 2; mi++)
                    mma_f16(acc[mi][ni][0], acc[mi][ni][1], acc[mi][ni][2], acc[mi][ni][3],
                            a[mi][0], a[mi][1], a[mi][2], a[mi][3], b0, b1);
            }
        }
        if (kt + 1 < nK) {
            const int ns = cs ^ 1;
            __half* Ad = smh + ns*QSTG_H;
            #pragma unroll
            for (int it = 0; it < 4; it++) {
                float4 v = areg[it];
                uint2 h2 = make_uint2(pk(v.x, v.y), pk(v.z, v.w));
                *reinterpret_cast<uint2*>(&Ad[(lrow+it*32)*QSA + lc4]) = h2;
            }
        }
        __syncthreads();
    }

    #pragma unroll
    for (int mi = 0; mi < 2; mi++) {
        const int rA = m0 + wm + mi*16 + g, rB = rA + 8;
        #pragma unroll
        for (int nj = 0; nj < 4; nj++) {
            const int c0 = wn + nj*16 + 2*t4;
            uint2 sA, sB;
            sA.x = pk(acc[mi][2*nj][0],   acc[mi][2*nj][1]);
            sB.x = pk(acc[mi][2*nj][2],   acc[mi][2*nj][3]);
            sA.y = pk(acc[mi][2*nj+1][0], acc[mi][2*nj+1][1]);
            sB.y = pk(acc[mi][2*nj+1][2], acc[mi][2*nj+1][3]);
            *reinterpret_cast<uint32_t*>(C + (size_t)rA*DHEAD + c0)     = sA.x;
            *reinterpret_cast<uint32_t*>(C + (size_t)rA*DHEAD + c0 + 8) = sA.y;
            *reinterpret_cast<uint32_t*>(C + (size_t)rB*DHEAD + c0)     = sB.x;
            *reinterpret_cast<uint32_t*>(C + (size_t)rB*DHEAD + c0 + 8) = sB.y;
        }
    }
}

// ---------------- flash attention (128-row KV tiles) ---------------------------
// 256 thr / 128 Q rows per CTA; KV tiles of 128 rows, double-buffered.
// Halves tile count (16 vs 32): half the barriers / l-shuffles / loop overhead.
#define SKV 136
#define FH_K 0
#define FH_V (2*128*SKV)
#define FL_SMEM_BYTES ((FH_V + 2*128*SKV)*2)   // 139264

__global__ __launch_bounds__(256) void flash_attn(
    const __half* __restrict__ q, const __half* __restrict__ k,
    const __half* __restrict__ v, float* __restrict__ outc,
    __half* __restrict__ outR)
{
    extern __shared__ char smraw[];
    __half* smh = (__half*)smraw;
    const uint32_t sm_u = s2u(smh);
    const int b   = blockIdx.y;
    const int qb  = blockIdx.x * 128;
    const int tid = threadIdx.x, lane = tid & 31, warp = tid >> 5;
    const int g   = lane >> 2, t4 = lane & 3;

    const __half* qB = q + ((size_t)b*SEQ + qb)*DHEAD;
    const __half* kB = k + (size_t)b*SEQ*DHEAD;
    const __half* vB = v + (size_t)b*SEQ*DHEAD;

    const int kc = tid >> 4;          // 0..15 (+16/iter, 8 iters -> 128 rows)
    const int kf = (tid & 15) * 8;

    const int krow = (lane >> 4)*8 + (lane & 7);
    const int kcol = ((lane >> 3) & 1) * 8;

    uint32_t qa[8][4];
    {
        const __half* q0 = qB + (size_t)(warp*16 + g)*DHEAD;
        const __half* q8 = q0 + 8*DHEAD;
        #pragma unroll
        for (int ks = 0; ks < 8; ks++) {
            const int o = ks*16 + 2*t4;
            qa[ks][0] = U32(q0 + o);
            qa[ks][1] = U32(q8 + o);
            qa[ks][2] = U32(q0 + o + 8);
            qa[ks][3] = U32(q8 + o + 8);
        }
    }

    float oacc[16][4];
    #pragma unroll
    for (int ni = 0; ni < 16; ni++)
        #pragma unroll
        for (int j = 0; j < 4; j++) oacc[ni][j] = 0.f;
    float l0 = 0.f, l1 = 0.f;

    {
        #pragma unroll
        for (int it = 0; it < 8; it++) {
            cp_async16(sm_u + (uint32_t)(FH_K + (kc + it*16)*SKV + kf)*2u,
                       kB + (size_t)(kc + it*16)*DHEAD + kf);
            cp_async16(sm_u + (uint32_t)(FH_V + (kc + it*16)*SKV + kf)*2u,
                       vB + (size_t)(kc + it*16)*DHEAD + kf);
        }
        CP_COMMIT();
    }

    const int nTiles = SEQ / 128;  // 16
    for (int t = 0; t < nTiles; t++) {
        const int cs = t & 1;
        if (t + 1 < nTiles) {
            const int ns = cs ^ 1;
            const int kv1 = (t+1) * 128;
            #pragma unroll
            for (int it = 0; it < 8; it++) {
                cp_async16(sm_u + (uint32_t)(FH_K + ns*128*SKV + (kc + it*16)*SKV + kf)*2u,
                           kB + (size_t)(kv1 + kc + it*16)*DHEAD + kf);
                cp_async16(sm_u + (uint32_t)(FH_V + ns*128*SKV + (kc + it*16)*SKV + kf)*2u,
                           vB + (size_t)(kv1 + kc + it*16)*DHEAD + kf);
            }
            CP_COMMIT();
            CP_WAIT(1);
        } else {
            CP_WAIT(0);
        }
        __syncthreads();

        const uint32_t kb0 = sm_u + (uint32_t)(FH_K + cs*128*SKV + krow*SKV + kcol)*2u;
        const uint32_t vb0 = sm_u + (uint32_t)(FH_V + cs*128*SKV + lane*SKV)*2u;

        // S = Q @ K^T (16 x 128 per warp)
        float sacc[16][4];
        #pragma unroll
        for (int ni = 0; ni < 16; ni++)
            #pragma unroll
            for (int j = 0; j < 4; j++) sacc[ni][j] = 0.f;
        #pragma unroll
        for (int ks = 0; ks < 8; ks++) {
            #pragma unroll
            for (int nj = 0; nj < 8; nj++) {
                uint32_t b0, b1, b2, b3;
                ldsm4(b0, b1, b2, b3, kb0 + (uint32_t)(nj*16*SKV + ks*16)*2u);
                mma_f16(sacc[2*nj][0], sacc[2*nj][1], sacc[2*nj][2], sacc[2*nj][3],
                        qa[ks][0], qa[ks][1], qa[ks][2], qa[ks][3], b0, b1);
                mma_f16(sacc[2*nj+1][0], sacc[2*nj+1][1], sacc[2*nj+1][2], sacc[2*nj+1][3],
                        qa[ks][0], qa[ks][1], qa[ks][2], qa[ks][3], b2, b3);
            }
        }

        // fixed-base softmax: P = exp2(s*scale*log2e - C); C cancels via l
        float rs0 = 0.f, rs1 = 0.f;
        uint32_t pa[8][4];
        #pragma unroll
        for (int j = 0; j < 8; j++) {
            const int n0i = 2*j, n1i = 2*j + 1;
            float p00 = ex2f(fmaf(sacc[n0i][0], SLG_F, -POFF_F));
            float p01 = ex2f(fmaf(sacc[n0i][1], SLG_F, -POFF_F));
            float p02 = ex2f(fmaf(sacc[n0i][2], SLG_F, -POFF_F));
            float p03 = ex2f(fmaf(sacc[n0i][3], SLG_F, -POFF_F));
            float p10 = ex2f(fmaf(sacc[n1i][0], SLG_F, -POFF_F));
            float p11 = ex2f(fmaf(sacc[n1i][1], SLG_F, -POFF_F));
            float p12 = ex2f(fmaf(sacc[n1i][2], SLG_F, -POFF_F));
            float p13 = ex2f(fmaf(sacc[n1i][3], SLG_F, -POFF_F));
            rs0 += p00 + p01 + p10 + p11;
            rs1 += p02 + p03 + p12 + p13;
            pa[j][0] = pk(p00, p01);
            pa[j][1] = pk(p02, p03);
            pa[j][2] = pk(p10, p11);
            pa[j][3] = pk(p12, p13);
        }
        rs0 += __shfl_xor_sync(0xffffffffu, rs0, 1);
        rs0 += __shfl_xor_sync(0xffffffffu, rs0, 2);
        rs1 += __shfl_xor_sync(0xffffffffu, rs1, 1);
        rs1 += __shfl_xor_sync(0xffffffffu, rs1, 2);
        l0 += rs0;
        l1 += rs1;

        // O += P @ V over 128 kv rows (4 groups of 32)
        #pragma unroll
        for (int jp = 0; jp < 4; jp++) {
            const uint32_t ab = vb0 + (uint32_t)(jp*32*SKV)*2u;
            #pragma unroll
            for (int ni = 0; ni < 16; ni++) {
                uint32_t b0, b1, b2, b3;
                ldsm4t(b0, b1, b2, b3, ab + ni*16);
                mma_f16(oacc[ni][0], oacc[ni][1], oacc[ni][2], oacc[ni][3],
                        pa[2*jp][0], pa[2*jp][1], pa[2*jp][2], pa[2*jp][3], b0, b1);
                mma_f16(oacc[ni][0], oacc[ni][1], oacc[ni][2], oacc[ni][3],
                        pa[2*jp+1][0], pa[2*jp+1][1], pa[2*jp+1][2], pa[2*jp+1][3], b2, b3);
            }
        }
        __syncthreads();
    }

    const float inv0 = 1.f / l0, inv1 = 1.f / l1;
    const size_t rowA = (size_t)b*SEQ + qb + warp*16 + g;
    const size_t rowB = rowA + 8;
    #pragma unroll
    for (int ni = 0; ni < 16; ni++) {
        const int c0 = ni*8 + 2*t4;
        float2 v0, v1;
        v0.x = oacc[ni][0]*inv0; v0.y = oacc[ni][1]*inv0;
        v1.x = oacc[ni][2]*inv1; v1.y = oacc[ni][3]*inv1;
        *reinterpret_cast<float2*>(outc + rowA*DHEAD + c0) = v0;
        *reinterpret_cast<float2*>(outc + rowB*DHEAD + c0) = v1;
        *reinterpret_cast<__half2*>(outR + rowA*DHEAD + c0) = __floats2half2_rn(v0.x, v0.y);
        *reinterpret_cast<__half2*>(outR + rowB*DHEAD + c0) = __floats2half2_rn(v1.x, v1.y);
    }
}

// ---------------- persistent merged rounds kernel (fp16, 256 thr, ldmatrix) ---
#define HSMS 136
#define RB_T0   0
#define RB_T1   34816
#define RB_T2   69632
#define RB_T3   104448
#define RB_T4   139264
#define RB_RED  174080
#define RB_ACT  176128
#define RALL_SMEM_BYTES (RB_ACT + 128*4)   // 176640
#define ZFS 132

__device__ __forceinline__ void load_tile128h(uint32_t sdst_bytes,
                                              const __half* __restrict__ src, int tid)
{
    const int row = tid >> 4, c8 = (tid & 15) * 8;
    #pragma unroll
    for (int it = 0; it < 8; it++)
        cp_async16(sdst_bytes + (uint32_t)((row + it*16)*HSMS + c8)*2u,
                   src + (size_t)(row + it*16)*128 + c8);
}

__device__ __forceinline__ void mma_128x128h(uint32_t aAddr, uint32_t bAddr,
                                             float acc[2][8][4])
{
    #pragma unroll
    for (int ks = 0; ks < 8; ks++) {
        uint32_t a[2][4];
        #pragma unroll
        for (int mi = 0; mi < 2; mi++)
            ldsm4(a[mi][0], a[mi][1], a[mi][2], a[mi][3],
                  aAddr + (uint32_t)(mi*16*HSMS + ks*16)*2u);
        #pragma unroll
        for (int nj = 0; nj < 4; nj++) {
            uint32_t b0, b1, b2, b3;
            ldsm4(b0, b1, b2, b3, bAddr + (uint32_t)(nj*16*HSMS + ks*16)*2u);
            #pragma unroll
            for (int mi = 0; mi < 2; mi++) {
                mma_f16(acc[mi][2*nj][0], acc[mi][2*nj][1], acc[mi][2*nj][2], acc[mi][2*nj][3],
                        a[mi][0], a[mi][1], a[mi][2], a[mi][3], b0, b1);
                mma_f16(acc[mi][2*nj+1][0], acc[mi][2*nj+1][1], acc[mi][2*nj+1][2], acc[mi][2*nj+1][3],
                        a[mi][0], a[mi][1], a[mi][2], a[mi][3], b2, b3);
            }
        }
    }
}

#define ZERO_ACC(acc) { \
    _Pragma("unroll") for (int mi = 0; mi < 2; mi++) \
        _Pragma("unroll") for (int ni = 0; ni < 8; ni++) \
            _Pragma("unroll") for (int j = 0; j < 4; j++) acc[mi][ni][j] = 0.f; }

__global__ __launch_bounds__(256) void rounds_all(
    float* __restrict__ cur, const __half* __restrict__ curR,
    const __half* __restrict__ tw, const __half* __restrict__ wd,
    const __half* __restrict__ w1c, const __half* __restrict__ w2,
    const float* __restrict__ cvec, const float* __restrict__ b1,
    const float* __restrict__ b2, const float* __restrict__ gw,
    const float* __restrict__ gb,
    int* __restrict__ cnt, int* __restrict__ anyf)
{
    extern __shared__ char smraw[];
    __half* smh = (__half*)smraw;
    const uint32_t sm_u = s2u(smraw);
    float* ZF  = reinterpret_cast<float*>(smraw + RB_T1);
    float* red = reinterpret_cast<float*>(smraw + RB_RED);
    int* s_act = reinterpret_cast<int*>(smraw + RB_ACT);
    __shared__ int s_flag, s_any;
    const int tid = threadIdx.x, lane = tid & 31, warp = tid >> 5;
    const int wm = (warp >> 1) * 32, wn = (warp & 1) * 64;
    const int g = lane >> 2, t4 = lane & 3;
    const int m0 = blockIdx.x * 128;

    const uint32_t aOff = (uint32_t)(((wm + (lane & 7) + 8*((lane >> 3) & 1))*HSMS
                                      + (lane >> 4)*8) * 2);
    const uint32_t bOff = (uint32_t)(((wn + (lane >> 4)*8 + (lane & 7))*HSMS
                                      + ((lane >> 3) & 1)*8) * 2);

    load_tile128h(sm_u + RB_T0, curR + (size_t)m0*128, tid);
    load_tile128h(sm_u + RB_T1, tw, tid);
    load_tile128h(sm_u + RB_T2, wd, tid);
    load_tile128h(sm_u + RB_T3, w1c, tid);
    load_tile128h(sm_u + RB_T4, w2, tid);
    CP_COMMIT(); CP_WAIT(0);
    if (tid < 128) s_act[tid] = 1;
    if (tid == 0) { s_flag = 1; s_any = 0; }
    __syncthreads();

    float acc[2][8][4];

    ZERO_ACC(acc);
    mma_128x128h(sm_u + RB_T0 + aOff, sm_u + RB_T1 + bOff, acc);
    __syncthreads();
    {
        __half* Ps = smh + RB_T1/2;
        #pragma unroll
        for (int mi = 0; mi < 2; mi++) {
            const int rA = wm + mi*16 + g, rB = rA + 8;
            #pragma unroll
            for (int ni = 0; ni < 8; ni++) {
                const int c0 = wn + ni*8 + 2*t4;
                *reinterpret_cast<__half2*>(&Ps[rA*HSMS + c0]) =
                    __floats2half2_rn(acc[mi][ni][0], acc[mi][ni][1]);
                *reinterpret_cast<__half2*>(&Ps[rB*HSMS + c0]) =
                    __floats2half2_rn(acc[mi][ni][2], acc[mi][ni][3]);
            }
        }
    }
    __syncthreads();
    ZERO_ACC(acc);
    mma_128x128h(sm_u + RB_T1 + aOff, sm_u + RB_T2 + bOff, acc);
    __syncthreads();
    {
        #pragma unroll
        for (int mi = 0; mi < 2; mi++) {
            const int rA = wm + mi*16 + g, rB = rA + 8;
            #pragma unroll
            for (int ni = 0; ni < 8; ni++) {
                const int c0 = wn + ni*8 + 2*t4;
                float2 v0, v1;
                v0.x = acc[mi][ni][0]; v0.y = acc[mi][ni][1];
                v1.x = acc[mi][ni][2]; v1.y = acc[mi][ni][3];
                *reinterpret_cast<float2*>(&ZF[rA*ZFS + c0]) = v0;
                *reinterpret_cast<float2*>(&ZF[rB*ZFS + c0]) = v1;
            }
        }
    }
    __syncthreads();

    for (int r = 0; r < NROUNDS; r++) {
        ZERO_ACC(acc);
        mma_128x128h(sm_u + RB_T0 + aOff, sm_u + RB_T3 + bOff, acc);
        __syncthreads();

        float amr[4];
        #pragma unroll
        for (int mi = 0; mi < 2; mi++) {
            const int rA = wm + mi*16 + g, rB = rA + 8;
            const float amA = s_act[rA] ? 1.f : 0.f;
            const float amB = s_act[rB] ? 1.f : 0.f;
            amr[mi*2] = amA; amr[mi*2+1] = amB;
            #pragma unroll
            for (int ni = 0; ni < 8; ni++) {
                const int c0 = wn + ni*8 + 2*t4;
                float2 zA = *reinterpret_cast<const float2*>(&ZF[rA*ZFS + c0]);
                float2 zB = *reinterpret_cast<const float2*>(&ZF[rB*ZFS + c0]);
                float2 cc = *reinterpret_cast<const float2*>(cvec + c0);
                float2 bb = *reinterpret_cast<const float2*>(b1 + c0);
                float h00 = fmaxf(fmaf(amA, acc[mi][ni][0] + zA.x + cc.x, bb.x), 0.f);
                float h01 = fmaxf(fmaf(amA, acc[mi][ni][1] + zA.y + cc.y, bb.y), 0.f);
                float h10 = fmaxf(fmaf(amB, acc[mi][ni][2] + zB.x + cc.x, bb.x), 0.f);
                float h11 = fmaxf(fmaf(amB, acc[mi][ni][3] + zB.y + cc.y, bb.y), 0.f);
                *reinterpret_cast<__half2*>(&smh[rA*HSMS + c0]) = __floats2half2_rn(h00, h01);
                *reinterpret_cast<__half2*>(&smh[rB*HSMS + c0]) = __floats2half2_rn(h10, h11);
            }
        }
        __syncthreads();

        ZERO_ACC(acc);
        mma_128x128h(sm_u + RB_T0 + aOff, sm_u + RB_T4 + bOff, acc);

        const int flg = s_flag;
        float d1[4] = {0,0,0,0}, nn[4] = {0,0,0,0};
        #pragma unroll
        for (int mi = 0; mi < 2; mi++) {
            const int rA = wm + mi*16 + g, rB = rA + 8;
            const float amA = amr[mi*2], amB = amr[mi*2+1];
            #pragma unroll
            for (int ni = 0; ni < 8; ni++) {
                const int c0 = wn + ni*8 + 2*t4;
                float2 cA = *reinterpret_cast<const float2*>(cur + (size_t)(m0+rA)*128 + c0);
                float2 cB = *reinterpret_cast<const float2*>(cur + (size_t)(m0+rB)*128 + c0);
                float2 bb = *reinterpret_cast<const float2*>(b2 + c0);
                float2 g1 = *reinterpret_cast<const float2*>(gw + c0);
                float2 g2 = *reinterpret_cast<const float2*>(gw + 128 + c0);
                float syA0 = acc[mi][ni][0] + bb.x, syA1 = acc[mi][ni][1] + bb.y;
                float syB0 = acc[mi][ni][2] + bb.x, syB1 = acc[mi][ni][3] + bb.y;
                float acA0 = cA.x * amA, acA1 = cA.y * amA;
                float acB0 = cB.x * amB, acB1 = cB.y * amB;
                d1[mi*2]   += acA0*g1.x + syA0*g2.x + acA1*g1.y + syA1*g2.y;
                d1[mi*2+1] += acB0*g1.x + syB0*g2.x + acB1*g1.y + syB1*g2.y;
                float dA0 = syA0-acA0, dA1 = syA1-acA1;
                float dB0 = syB0-acB0, dB1 = syB1-acB1;
                nn[mi*2]   += dA0*dA0 + dA1*dA1;
                nn[mi*2+1] += dB0*dB0 + dB1*dB1;
            }
        }
        #pragma unroll
        for (int j = 0; j < 4; j++) {
            d1[j] += __shfl_xor_sync(0xffffffffu, d1[j], 1);
            d1[j] += __shfl_xor_sync(0xffffffffu, d1[j], 2);
            nn[j] += __shfl_xor_sync(0xffffffffu, nn[j], 1);
            nn[j] += __shfl_xor_sync(0xffffffffu, nn[j], 2);
        }
        if (t4 == 0) {
            const int hf = (warp & 1) * 2;
            #pragma unroll
            for (int mi = 0; mi < 2; mi++) {
                const int rA = wm + mi*16 + g, rB = rA + 8;
                red[rA*4 + hf]     = d1[mi*2];
                red[rA*4 + hf + 1] = nn[mi*2];
                red[rB*4 + hf]     = d1[mi*2+1];
                red[rB*4 + hf + 1] = nn[mi*2+1];
            }
        }
        __syncthreads();

        const float gbv = gb[0];
        #pragma unroll
        for (int mi = 0; mi < 2; mi++) {
            const int rA = wm + mi*16 + g, rB = rA + 8;
            const float amA = amr[mi*2], amB = amr[mi*2+1];
            float gdA = red[rA*4+0] + red[rA*4+2] + gbv;
            float gdB = red[rB*4+0] + red[rB*4+2] + gbv;
            float n2A = red[rA*4+1] + red[rA*4+3];
            float n2B = red[rB*4+1] + red[rB*4+3];
            float gateA = sigmoidf_fast(gdA);
            float gateB = sigmoidf_fast(gdB);
            int stableA = (gateA * 0.1f * sqrtf(n2A)) < 0.1f;
            int stableB = (gateB * 0.1f * sqrtf(n2B)) < 0.1f;
            #pragma unroll
            for (int ni = 0; ni < 8; ni++) {
                const int c0 = wn + ni*8 + 2*t4;
                float2 cA = *reinterpret_cast<const float2*>(cur + (size_t)(m0+rA)*128 + c0);
                float2 cB = *reinterpret_cast<const float2*>(cur + (size_t)(m0+rB)*128 + c0);
                float2 bb = *reinterpret_cast<const float2*>(b2 + c0);
                float syA0 = acc[mi][ni][0] + bb.x, syA1 = acc[mi][ni][1] + bb.y;
                float syB0 = acc[mi][ni][2] + bb.x, syB1 = acc[mi][ni][3] + bb.y;
                float2 o0, o1;
                o0.x = cA.x; o0.y = cA.y; o1.x = cB.x; o1.y = cB.y;
                if (flg) {
                    o0.x += gateA * (syA0 - cA.x*amA) * 0.1f;
                    o0.y += gateA * (syA1 - cA.y*amA) * 0.1f;
                    o1.x += gateB * (syB0 - cB.x*amB) * 0.1f;
                    o1.y += gateB * (syB1 - cB.y*amB) * 0.1f;
                }
                *reinterpret_cast<float2*>(cur + (size_t)(m0+rA)*128 + c0) = o0;
                *reinterpret_cast<float2*>(cur + (size_t)(m0+rB)*128 + c0) = o1;
                *reinterpret_cast<__half2*>(&smh[rA*HSMS + c0]) = __floats2half2_rn(o0.x, o0.y);
                *reinterpret_cast<__half2*>(&smh[rB*HSMS + c0]) = __floats2half2_rn(o1.x, o1.y);
            }
            if ((warp & 1) == 0 && t4 == 0) {
                int actA = amA > 0.f, actB = amB > 0.f;
                int naA = actA && !stableA;
                int naB = actB && !stableB;
                if (flg) { s_act[rA] = naA; s_act[rB] = naB; }
                int effA = flg ? naA : actA;
                int effB = flg ? naB : actB;
                if (effA | effB) s_any = 1;
            }
        }
        __syncthreads();

        if (r + 1 < NROUNDS) {
            if (tid == 0) {
                if (s_any) atomicOr(&anyf[r], 1);
                __threadfence();
                atomicAdd(&cnt[r], 1);
                while (atomicAdd(&cnt[r], 0) < (int)gridDim.x) {}
                s_flag = (atomicOr(&anyf[r], 0) != 0) ? 1 : 0;
                s_any = 0;
            }
            __syncthreads();
        }
    }
}

// ---------------- single prep kernel (fp16 weight copies) ---------------------
__global__ void prep_all(
    const float* __restrict__ wq, const float* __restrict__ wk,
    const float* __restrict__ wv, const float* __restrict__ tw,
    const float* __restrict__ w2, const float* __restrict__ w1,
    const float* __restrict__ tb, const float* __restrict__ ab,
    __half* __restrict__ wqkvr, __half* __restrict__ twr,
    __half* __restrict__ w2r, __half* __restrict__ wdr,
    __half* __restrict__ w1cr, float* __restrict__ cvec,
    int* __restrict__ cnt, int* __restrict__ anyf)
{
    int idx = blockIdx.x * blockDim.x + threadIdx.x;
    const int WN4 = DHEAD*DMODEL/4;
    const int T4  = DHEAD*DHEAD/4;
    if (idx < 3*WN4) {
        const float* src = (idx < WN4) ? wq : (idx < 2*WN4 ? wk : wv);
        int off = (idx < WN4) ? idx : (idx < 2*WN4 ? idx - WN4 : idx - 2*WN4);
        float4 vv = reinterpret_cast<const float4*>(src)[off];
        reinterpret_cast<__half2*>(wqkvr)[2*idx]   = __floats2half2_rn(vv.x, vv.y);
        reinterpret_cast<__half2*>(wqkvr)[2*idx+1] = __floats2half2_rn(vv.z, vv.w);
        return;
    }
    idx -= 3*WN4;
    if (idx < T4) {
        float4 vv = reinterpret_cast<const float4*>(tw)[idx];
        reinterpret_cast<__half2*>(twr)[2*idx]   = __floats2half2_rn(vv.x, vv.y);
        reinterpret_cast<__half2*>(twr)[2*idx+1] = __floats2half2_rn(vv.z, vv.w);
        return;
    }
    idx -= T4;
    if (idx < T4) {
        float4 vv = reinterpret_cast<const float4*>(w2)[idx];
        reinterpret_cast<__half2*>(w2r)[2*idx]   = __floats2half2_rn(vv.x, vv.y);
        reinterpret_cast<__half2*>(w2r)[2*idx+1] = __floats2half2_rn(vv.z, vv.w);
        return;
    }
    idx -= T4;
    if (idx < DHEAD*DHEAD) {
        int j = idx >> 7, i = idx & 127;
        wdr[idx]  = __float2half_rn(w1[j*384 + i] - w1[j*384 + 128 + i]);
        w1cr[idx] = __float2half_rn(w1[j*384 + 256 + i]);
        return;
    }
    idx -= DHEAD*DHEAD;
    if (idx < DHEAD) {
        float s = 0.f;
        for (int i = 0; i < 128; i++)
            s += tb[i]*w1[idx*384 + i] + ab[i]*w1[idx*384 + 128 + i];
        cvec[idx] = s;
        return;
    }
    idx -= DHEAD;
    if (idx < NROUNDS) { cnt[idx] = 0; return; }
    idx -= NROUNDS;
    if (idx < NROUNDS) { anyf[idx] = 0; return; }
}
#define PREP_ITEMS (3*(DHEAD*DMODEL/4) + 2*(DHEAD*DHEAD/4) + DHEAD*DHEAD + DHEAD + 2*NROUNDS)

// ---------------- launch ------------------------------------------------------
extern "C" void kernel_launch(void* const* d_in, const int* in_sizes, int n_in,
                              void* d_out, int out_size)
{
    (void)in_sizes; (void)n_in; (void)out_size;
    const float* x  = (const float*)d_in[0];
    const float* wq = (const float*)d_in[1];
    const float* wk = (const float*)d_in[2];
    const float* wv = (const float*)d_in[3];
    const float* tw = (const float*)d_in[4];
    const float* tb = (const float*)d_in[5];
    const float* ab = (const float*)d_in[6];
    const float* w1 = (const float*)d_in[7];
    const float* b1 = (const float*)d_in[8];
    const float* w2 = (const float*)d_in[9];
    const float* b2 = (const float*)d_in[10];
    const float* gw = (const float*)d_in[11];
    const float* gb = (const float*)d_in[12];
    float* cur = (float*)d_out;

    __half *qkv,*curR,*wqkvr,*twr,*w2r,*wdr,*w1cr;
    float *cvec;
    int *cnt,*anyf;
    cudaGetSymbolAddress((void**)&qkv,    g_qkv);
    cudaGetSymbolAddress((void**)&curR,   g_curR);
    cudaGetSymbolAddress((void**)&wqkvr,  g_wqkvr);
    cudaGetSymbolAddress((void**)&twr,    g_twr);
    cudaGetSymbolAddress((void**)&w2r,    g_w2r);
    cudaGetSymbolAddress((void**)&wdr,    g_wdr);
    cudaGetSymbolAddress((void**)&w1cr,   g_w1cr);
    cudaGetSymbolAddress((void**)&cvec,   g_cvec);
    cudaGetSymbolAddress((void**)&cnt,    g_cnt);
    cudaGetSymbolAddress((void**)&anyf,   g_any);

    cudaFuncSetAttribute(qkv_gemm,   cudaFuncAttributeMaxDynamicSharedMemorySize, QKV_SMEM_BYTES);
    cudaFuncSetAttribute(flash_attn, cudaFuncAttributeMaxDynamicSharedMemorySize, FL_SMEM_BYTES);
    cudaFuncSetAttribute(rounds_all, cudaFuncAttributeMaxDynamicSharedMemorySize, RALL_SMEM_BYTES);

    prep_all<<<(PREP_ITEMS + 255)/256, 256>>>(
        wq, wk, wv, tw, w2, w1, tb, ab,
        wqkvr, twr, w2r, wdr, w1cr, cvec, cnt, anyf);

    qkv_gemm<<<dim3(3, MTOK/128), 256, QKV_SMEM_BYTES>>>(x, wqkvr, qkv);

    flash_attn<<<dim3(SEQ/128, BATCH), 256, FL_SMEM_BYTES>>>(
        qkv, qkv + (size_t)MTOK*DHEAD, qkv + 2*(size_t)MTOK*DHEAD, cur, curR);

    rounds_all<<<MTOK/128, 256, RALL_SMEM_BYTES>>>(
        cur, curR, twr, wdr, w1cr, w2r, cvec, b1, b2, gw, gb, cnt, anyf);
}